// round 15
// baseline (speedup 1.0000x reference)
#include <cuda_runtime.h>
#include <cuda_fp16.h>
#include <cstdint>
#include <math.h>

#define E_BONDS   131072
#define N_ATOMS_  65536
#define HID       256
#define AFD       143
#define KIN       157
#define KIN_P     160
#define KCAT_P    416
#define BMOL      2048

#define EH  ((size_t)E_BONDS * HID)
#define NH  ((size_t)N_ATOMS_ * HID)
__device__ float g_scratch[127 * 1024 * 1024];

__device__ __forceinline__ uint32_t smem_u32(const void* p) {
    uint32_t a;
    asm("{ .reg .u64 t; cvta.to.shared.u64 t, %1; cvt.u32.u64 %0, t; }"
        : "=r"(a) : "l"(p));
    return a;
}
__device__ __forceinline__ void cp_async16(uint32_t dst, const void* src) {
    asm volatile("cp.async.cg.shared.global [%0], [%1], 16;"
                 :: "r"(dst), "l"(src));
}
#define CP_COMMIT() asm volatile("cp.async.commit_group;" ::: "memory")
#define CP_WAIT0()  asm volatile("cp.async.wait_group 0;" ::: "memory")
#define CP_WAIT1()  asm volatile("cp.async.wait_group 1;" ::: "memory")
#define CP_WAIT2()  asm volatile("cp.async.wait_group 2;" ::: "memory")

// ---------------------------------------------------------------------------
// conversions / padding
// ---------------------------------------------------------------------------
__global__ void w2h_all(const float* __restrict__ s1, const float* __restrict__ s3,
                        const float* __restrict__ s4, __half* __restrict__ dst,
                        float* __restrict__ zbuf, int zn)
{
    int i = blockIdx.x * 256 + threadIdx.x;
    if (i < zn) zbuf[i] = 0.f;
    const int n1 = HID * 256, n3 = 2 * HID * 256, n4 = 3 * HID * 256;
    if (i >= n4) return;
    float v;
    if      (i < n1) v = s1[i];
    else if (i < n3) v = s3[i - n1];
    else             v = s4[i - n3];
    dst[i] = __float2half(v);
}

__global__ void build_wi(const float* __restrict__ W, __half* __restrict__ dst)
{
    int i = blockIdx.x * 256 + threadIdx.x;
    if (i >= KIN_P * 256) return;
    const int r = i >> 8;
    dst[i] = __float2half(r < KIN ? W[i] : 0.f);
}

__global__ void build_wo(const float* __restrict__ W, __half* __restrict__ dst)
{
    int i = blockIdx.x * 256 + threadIdx.x;
    if (i >= KCAT_P * 256) return;
    const int r = i >> 8, c = i & 255;
    float v = 0.f;
    if (r < 143)                  v = W[r * 256 + c];
    else if (r >= 144 && r < 400) v = W[(r - 1) * 256 + c];
    dst[i] = __float2half(v);
}

__global__ void fb_conv(const float* __restrict__ fb, __half* __restrict__ dst)
{
    int i = blockIdx.x * 256 + threadIdx.x;
    if (i >= E_BONDS * 20) return;
    const int e = i / 20, g = i - e * 20;
    const float* src = fb + (size_t)e * KIN + g * 8;
    __align__(16) __half hb[8];
#pragma unroll
    for (int k = 0; k < 8; k++) {
        const int c = g * 8 + k;
        hb[k] = __float2half(c < KIN ? src[k] : 0.f);
    }
    *(uint4*)&dst[(size_t)e * KIN_P + g * 8] = *(uint4*)hb;
}

// ---------------------------------------------------------------------------
// hgemm: 4-stage cp.async ring, K-chunk 32, block 128x128 (grid.y=2), fp16 A
// ATTSUM: per-molecule column sums of post-relu rows -> attsum[mol][col]
// ---------------------------------------------------------------------------
#define LDA_H 40
#define LDB_H 136
#define SA_EL (128 * LDA_H)
#define SB_EL (32 * LDB_H)
#define ST_EL (SA_EL + SB_EL)
#define HG_SMEM (4 * ST_EL * 2)

template<bool HAS_BIAS, bool RELU, bool OUTH, bool RAWH, bool SCOREF, bool ATTSUM>
__global__ void __launch_bounds__(256, 2) hgemm(
    int M, int K,
    const __half* __restrict__ Ah, int ldah,
    const __half* __restrict__ B,
    const float* __restrict__ bias,
    __half* __restrict__ outh,
    __half* __restrict__ rawh,
    const float* __restrict__ wma,
    float* __restrict__ scores_out,
    float* __restrict__ attsum)
{
    extern __shared__ __align__(16) __half smh[];

    const int tid  = threadIdx.x;
    const int wid  = tid >> 5;
    const int lane = tid & 31;
    const int m0   = blockIdx.x * 128;
    const int n0   = blockIdx.y * 128;
    const int wm   = (wid & 3) * 32;
    const int wn   = (wid >> 2) * 64;
    const int S    = K >> 5;

    float acc[2][8][4];
#pragma unroll
    for (int t = 0; t < 2; t++)
#pragma unroll
        for (int j = 0; j < 8; j++)
#pragma unroll
            for (int q = 0; q < 4; q++) acc[t][j][q] = 0.f;

    const int lrow = lane & 15;
    const int lcof = (lane >> 4) * 8;

    auto stage = [&](int s) {
        const int k0 = s * 32;
        __half* bA = smh + (s & 3) * ST_EL;
        __half* bB = bA + SA_EL;
#pragma unroll
        for (int it = 0; it < 2; it++) {
            const int id = tid + it * 256;
            const int r  = id >> 4;
            const int c8 = (id & 15) * 8;
            cp_async16(smem_u32(&bB[r * LDB_H + c8]),
                       &B[(size_t)(k0 + r) * 256 + n0 + c8]);
        }
#pragma unroll
        for (int it = 0; it < 2; it++) {
            const int id  = tid + it * 256;
            const int r   = id >> 2;
            const int c16 = (id & 3) * 8;
            cp_async16(smem_u32(&bA[r * LDA_H + c16]),
                       &Ah[(size_t)(m0 + r) * ldah + k0 + c16]);
        }
        CP_COMMIT();
    };

#pragma unroll
    for (int p = 0; p < 3; p++) {
        if (p < S) stage(p); else CP_COMMIT();
    }

    for (int s = 0; s < S; s++) {
        CP_WAIT2();
        __syncthreads();
        if (s + 3 < S) stage(s + 3); else CP_COMMIT();

        __half* bA = smh + (s & 3) * ST_EL;
        __half* bB = bA + SA_EL;
#pragma unroll
        for (int ks = 0; ks < 2; ks++) {
            uint32_t fa[2][4];
#pragma unroll
            for (int t = 0; t < 2; t++) {
                const uint32_t ad = smem_u32(&bA[(wm + t * 16 + lrow) * LDA_H + ks * 16 + lcof]);
                asm volatile("ldmatrix.sync.aligned.m8n8.x4.shared.b16 {%0,%1,%2,%3}, [%4];"
                             : "=r"(fa[t][0]), "=r"(fa[t][1]), "=r"(fa[t][2]), "=r"(fa[t][3])
                             : "r"(ad));
            }
            uint32_t fb[8][2];
#pragma unroll
            for (int nt = 0; nt < 4; nt++) {
                const uint32_t ad = smem_u32(&bB[(ks * 16 + lrow) * LDB_H + wn + nt * 16 + lcof]);
                uint32_t r0, r1, r2, r3;
                asm volatile("ldmatrix.sync.aligned.m8n8.x4.trans.shared.b16 {%0,%1,%2,%3}, [%4];"
                             : "=r"(r0), "=r"(r1), "=r"(r2), "=r"(r3) : "r"(ad));
                fb[nt * 2][0] = r0; fb[nt * 2][1] = r1;
                fb[nt * 2 + 1][0] = r2; fb[nt * 2 + 1][1] = r3;
            }
#pragma unroll
            for (int t = 0; t < 2; t++)
#pragma unroll
                for (int j = 0; j < 8; j++)
                    asm volatile(
                        "mma.sync.aligned.m16n8k16.row.col.f32.f16.f16.f32 "
                        "{%0,%1,%2,%3}, {%4,%5,%6,%7}, {%8,%9}, {%0,%1,%2,%3};"
                        : "+f"(acc[t][j][0]), "+f"(acc[t][j][1]),
                          "+f"(acc[t][j][2]), "+f"(acc[t][j][3])
                        : "r"(fa[t][0]), "r"(fa[t][1]), "r"(fa[t][2]), "r"(fa[t][3]),
                          "r"(fb[j][0]), "r"(fb[j][1]));
        }
    }

    float rowdot[2][2] = {{0.f, 0.f}, {0.f, 0.f}};
    float colsum[8][2];
    if (ATTSUM)
#pragma unroll
        for (int j = 0; j < 8; j++) { colsum[j][0] = 0.f; colsum[j][1] = 0.f; }

#pragma unroll
    for (int t = 0; t < 2; t++) {
        const int mrow = m0 + wm + t * 16 + (lane >> 2);
#pragma unroll
        for (int j = 0; j < 8; j++) {
            const int nc = n0 + wn + j * 8 + (lane & 3) * 2;
            float wx = 0.f, wy = 0.f;
            if (SCOREF) { wx = __ldg(&wma[nc]); wy = __ldg(&wma[nc + 1]); }
#pragma unroll
            for (int hf = 0; hf < 2; hf++) {
                const size_t m = (size_t)(mrow + hf * 8);
                float vx = acc[t][j][hf * 2 + 0];
                float vy = acc[t][j][hf * 2 + 1];
                if (HAS_BIAS) { vx += bias[nc]; vy += bias[nc + 1]; }
                if (RAWH) *(__half2*)&rawh[m * 256 + nc] = __floats2half2_rn(vx, vy);
                if (RELU) { vx = fmaxf(vx, 0.f); vy = fmaxf(vy, 0.f); }
                if (OUTH) *(__half2*)&outh[m * 256 + nc] = __floats2half2_rn(vx, vy);
                if (SCOREF) rowdot[t][hf] += vx * wx + vy * wy;
                if (ATTSUM) { colsum[j][0] += vx; colsum[j][1] += vy; }
            }
        }
    }
    if (SCOREF) {
#pragma unroll
        for (int t = 0; t < 2; t++)
#pragma unroll
            for (int hf = 0; hf < 2; hf++) {
                float v = rowdot[t][hf];
                v += __shfl_xor_sync(0xffffffffu, v, 1);
                v += __shfl_xor_sync(0xffffffffu, v, 2);
                if ((lane & 3) == 0)
                    atomicAdd(&scores_out[m0 + wm + t * 16 + hf * 8 + (lane >> 2)], v);
            }
    }
    if (ATTSUM) {
        const int mol = (m0 >> 5) + (wid & 3);   // warp-m tile = 1 molecule
#pragma unroll
        for (int j = 0; j < 8; j++) {
            float cx = colsum[j][0], cy = colsum[j][1];
#pragma unroll
            for (int o = 4; o <= 16; o <<= 1) {
                cx += __shfl_xor_sync(0xffffffffu, cx, o);
                cy += __shfl_xor_sync(0xffffffffu, cy, o);
            }
            if ((lane >> 2) == 0) {
                const int nc = n0 + wn + j * 8 + (lane & 3) * 2;
                *(float2*)&attsum[(size_t)mol * 256 + nc] = make_float2(cx, cy);
            }
        }
    }
}

// ---------------------------------------------------------------------------
// FUSED message-passing step: K-chunk 64, 2-stage B ring, 2 CTAs/SM
// ---------------------------------------------------------------------------
#define MP_LDA 264
#define MP_LDB 264
#define MP_SA   (64 * MP_LDA)
#define MP_SB64 (64 * MP_LDB)
#define MP_SMEM ((MP_SA + 2 * MP_SB64) * 2)   // 101376 bytes

__global__ void __launch_bounds__(256, 2) mp_step(
    const __half* __restrict__ msg, const int* __restrict__ bgraph,
    const float* __restrict__ scores, const __half* __restrict__ Wh,
    const __half* __restrict__ binput, __half* __restrict__ msg_out,
    const float* __restrict__ wma, float* __restrict__ scores_out)
{
    extern __shared__ __align__(16) __half smh[];
    __shared__ float sred[64];
    __half* sA = smh;
    __half* sBr = smh + MP_SA;

    const int tid  = threadIdx.x;
    const int wid  = tid >> 5;
    const int lane = tid & 31;
    const int e0   = blockIdx.x * 64;
    const int wm   = (wid & 1) * 32;
    const int wn   = (wid >> 1) * 64;

    if (tid < 64) sred[tid] = 0.f;

    auto stageB = [&](int s) {        // K-chunk 64
        const int k0 = s * 64;
        __half* bB = sBr + (s & 1) * MP_SB64;
#pragma unroll
        for (int it = 0; it < 8; it++) {
            const int id = tid + it * 256;       // 0..2047
            const int r  = id >> 5;              // 0..63
            const int c8 = (id & 31) * 8;
            cp_async16(smem_u32(&bB[r * MP_LDB + c8]),
                       &Wh[(size_t)(k0 + r) * 256 + c8]);
        }
        CP_COMMIT();
    };

    stageB(0); stageB(1);            // both overlap the gather

    // ---- gather: 2-row software pipeline ----
    {
        int   idxr[8];
        float scr[8];
#pragma unroll
        for (int rr = 0; rr < 8; rr++) {
            const int e = e0 + wid * 8 + rr;
            int id = 0; float sc = 0.f;
            if (lane < 6) {
                id = bgraph[e * 6 + lane];
                sc = __ldg(&scores[id]);
            }
            idxr[rr] = id; scr[rr] = sc;
        }
#pragma unroll
        for (int pr = 0; pr < 4; pr++) {
            const int r0 = pr * 2, r1 = pr * 2 + 1;
            int   nb0[6], nb1[6];
            float s0[6], s1[6];
#pragma unroll
            for (int j = 0; j < 6; j++) {
                nb0[j] = __shfl_sync(0xffffffffu, idxr[r0], j);
                s0[j]  = __shfl_sync(0xffffffffu, scr[r0], j);
                nb1[j] = __shfl_sync(0xffffffffu, idxr[r1], j);
                s1[j]  = __shfl_sync(0xffffffffu, scr[r1], j);
            }
            uint4 rv0[6], rv1[6];
#pragma unroll
            for (int j = 0; j < 6; j++)
                rv0[j] = *(const uint4*)(msg + (size_t)nb0[j] * 256 + lane * 8);
#pragma unroll
            for (int j = 0; j < 6; j++)
                rv1[j] = *(const uint4*)(msg + (size_t)nb1[j] * 256 + lane * 8);

            float w0[6], w1[6];
            {
                float mx0 = s0[0], mx1 = s1[0];
#pragma unroll
                for (int j = 1; j < 6; j++) { mx0 = fmaxf(mx0, s0[j]); mx1 = fmaxf(mx1, s1[j]); }
                float sum0 = 0.f, sum1 = 0.f;
#pragma unroll
                for (int j = 0; j < 6; j++) {
                    w0[j] = expf(s0[j] - mx0); sum0 += w0[j];
                    w1[j] = expf(s1[j] - mx1); sum1 += w1[j];
                }
                const float i0 = 1.0f / sum0, i1 = 1.0f / sum1;
#pragma unroll
                for (int j = 0; j < 6; j++) { w0[j] *= i0; w1[j] *= i1; }
            }

            float a0[8] = {0,0,0,0,0,0,0,0}, a1[8] = {0,0,0,0,0,0,0,0};
#pragma unroll
            for (int j = 0; j < 6; j++) {
                const float2 f0 = __half22float2(*(const __half2*)&rv0[j].x);
                const float2 f1 = __half22float2(*(const __half2*)&rv0[j].y);
                const float2 f2 = __half22float2(*(const __half2*)&rv0[j].z);
                const float2 f3 = __half22float2(*(const __half2*)&rv0[j].w);
                a0[0] += w0[j] * f0.x; a0[1] += w0[j] * f0.y;
                a0[2] += w0[j] * f1.x; a0[3] += w0[j] * f1.y;
                a0[4] += w0[j] * f2.x; a0[5] += w0[j] * f2.y;
                a0[6] += w0[j] * f3.x; a0[7] += w0[j] * f3.y;
            }
#pragma unroll
            for (int j = 0; j < 6; j++) {
                const float2 f0 = __half22float2(*(const __half2*)&rv1[j].x);
                const float2 f1 = __half22float2(*(const __half2*)&rv1[j].y);
                const float2 f2 = __half22float2(*(const __half2*)&rv1[j].z);
                const float2 f3 = __half22float2(*(const __half2*)&rv1[j].w);
                a1[0] += w1[j] * f0.x; a1[1] += w1[j] * f0.y;
                a1[2] += w1[j] * f1.x; a1[3] += w1[j] * f1.y;
                a1[4] += w1[j] * f2.x; a1[5] += w1[j] * f2.y;
                a1[6] += w1[j] * f3.x; a1[7] += w1[j] * f3.y;
            }
            uint4 ov;
            *(__half2*)&ov.x = __floats2half2_rn(a0[0], a0[1]);
            *(__half2*)&ov.y = __floats2half2_rn(a0[2], a0[3]);
            *(__half2*)&ov.z = __floats2half2_rn(a0[4], a0[5]);
            *(__half2*)&ov.w = __floats2half2_rn(a0[6], a0[7]);
            *(uint4*)&sA[(wid * 8 + r0) * MP_LDA + lane * 8] = ov;
            *(__half2*)&ov.x = __floats2half2_rn(a1[0], a1[1]);
            *(__half2*)&ov.y = __floats2half2_rn(a1[2], a1[3]);
            *(__half2*)&ov.z = __floats2half2_rn(a1[4], a1[5]);
            *(__half2*)&ov.w = __floats2half2_rn(a1[6], a1[7]);
            *(uint4*)&sA[(wid * 8 + r1) * MP_LDA + lane * 8] = ov;
        }
    }

    float acc[2][8][4];
#pragma unroll
    for (int t = 0; t < 2; t++)
#pragma unroll
        for (int j = 0; j < 8; j++)
#pragma unroll
            for (int q = 0; q < 4; q++) acc[t][j][q] = 0.f;

    const int lrow = lane & 15;
    const int lcof = (lane >> 4) * 8;

    for (int s = 0; s < 4; s++) {     // K = 256, chunk 64
        if (s == 0) CP_WAIT1(); else CP_WAIT0();
        __syncthreads();
        if (s >= 1 && s + 1 < 4) stageB(s + 1);

        __half* bB = sBr + (s & 1) * MP_SB64;
#pragma unroll
        for (int ks = 0; ks < 4; ks++) {
            const int kcol = s * 64 + ks * 16;
            uint32_t fa[2][4];
#pragma unroll
            for (int t = 0; t < 2; t++) {
                const uint32_t ad = smem_u32(&sA[(wm + t * 16 + lrow) * MP_LDA + kcol + lcof]);
                asm volatile("ldmatrix.sync.aligned.m8n8.x4.shared.b16 {%0,%1,%2,%3}, [%4];"
                             : "=r"(fa[t][0]), "=r"(fa[t][1]), "=r"(fa[t][2]), "=r"(fa[t][3])
                             : "r"(ad));
            }
            uint32_t fb[8][2];
#pragma unroll
            for (int nt = 0; nt < 4; nt++) {
                const uint32_t ad = smem_u32(&bB[(ks * 16 + lrow) * MP_LDB + wn + nt * 16 + lcof]);
                uint32_t r0, r1, r2, r3;
                asm volatile("ldmatrix.sync.aligned.m8n8.x4.trans.shared.b16 {%0,%1,%2,%3}, [%4];"
                             : "=r"(r0), "=r"(r1), "=r"(r2), "=r"(r3) : "r"(ad));
                fb[nt * 2][0] = r0; fb[nt * 2][1] = r1;
                fb[nt * 2 + 1][0] = r2; fb[nt * 2 + 1][1] = r3;
            }
#pragma unroll
            for (int t = 0; t < 2; t++)
#pragma unroll
                for (int j = 0; j < 8; j++)
                    asm volatile(
                        "mma.sync.aligned.m16n8k16.row.col.f32.f16.f16.f32 "
                        "{%0,%1,%2,%3}, {%4,%5,%6,%7}, {%8,%9}, {%0,%1,%2,%3};"
                        : "+f"(acc[t][j][0]), "+f"(acc[t][j][1]),
                          "+f"(acc[t][j][2]), "+f"(acc[t][j][3])
                        : "r"(fa[t][0]), "r"(fa[t][1]), "r"(fa[t][2]), "r"(fa[t][3]),
                          "r"(fb[j][0]), "r"(fb[j][1]));
        }
    }

    float rowdot[2][2] = {{0.f, 0.f}, {0.f, 0.f}};
#pragma unroll
    for (int t = 0; t < 2; t++) {
        const int mrow = e0 + wm + t * 16 + (lane >> 2);
#pragma unroll
        for (int j = 0; j < 8; j++) {
            const int nc = wn + j * 8 + (lane & 3) * 2;
            const float wx = __ldg(&wma[nc]);
            const float wy = __ldg(&wma[nc + 1]);
#pragma unroll
            for (int hf = 0; hf < 2; hf++) {
                const size_t m = (size_t)(mrow + hf * 8);
                float vx = acc[t][j][hf * 2 + 0];
                float vy = acc[t][j][hf * 2 + 1];
                const float2 d = __half22float2(*(const __half2*)&binput[m * 256 + nc]);
                vx = fmaxf(vx + d.x, 0.f);
                vy = fmaxf(vy + d.y, 0.f);
                *(__half2*)&msg_out[m * 256 + nc] = __floats2half2_rn(vx, vy);
                rowdot[t][hf] += vx * wx + vy * wy;
            }
        }
    }
    if (scores_out) {
#pragma unroll
        for (int t = 0; t < 2; t++)
#pragma unroll
            for (int hf = 0; hf < 2; hf++) {
                float v = rowdot[t][hf];
                v += __shfl_xor_sync(0xffffffffu, v, 1);
                v += __shfl_xor_sync(0xffffffffu, v, 2);
                if ((lane & 3) == 0)
                    atomicAdd(&sred[wm + t * 16 + hf * 8 + (lane >> 2)], v);
            }
        __syncthreads();
        if (tid < 64) scores_out[e0 + tid] = sred[tid];
    }
}

// ---------------------------------------------------------------------------
// atom_gather + fused fatoms conversion
// ---------------------------------------------------------------------------
__global__ void __launch_bounds__(256) atom_gather(
    const __half* __restrict__ msg, const int* __restrict__ agraph,
    const float* __restrict__ fa, __half* __restrict__ cat)
{
    const int ga   = (blockIdx.x * 256 + threadIdx.x) >> 5;
    const int lane = threadIdx.x & 31;
    if (ga >= N_ATOMS_) return;

    if (lane < 18) {
        const float* src = fa + (size_t)ga * AFD + lane * 8;
        __align__(16) __half hb[8];
#pragma unroll
        for (int k = 0; k < 8; k++) {
            const int c = lane * 8 + k;
            hb[k] = __float2half(c < AFD ? src[k] : 0.f);
        }
        *(uint4*)&cat[(size_t)ga * KCAT_P + lane * 8] = *(uint4*)hb;
    } else if (lane < 20) {
        uint4 z = make_uint4(0, 0, 0, 0);
        *(uint4*)&cat[(size_t)ga * KCAT_P + 400 + (lane - 18) * 8] = z;
    }

    float a[8] = {0, 0, 0, 0, 0, 0, 0, 0};
#pragma unroll
    for (int j = 0; j < 6; j++) {
        const int nb = agraph[ga * 6 + j];
        const uint4 rv = *(const uint4*)(msg + (size_t)nb * 256 + lane * 8);
        const float2 f0 = __half22float2(*(const __half2*)&rv.x);
        const float2 f1 = __half22float2(*(const __half2*)&rv.y);
        const float2 f2 = __half22float2(*(const __half2*)&rv.z);
        const float2 f3 = __half22float2(*(const __half2*)&rv.w);
        a[0] += f0.x; a[1] += f0.y; a[2] += f1.x; a[3] += f1.y;
        a[4] += f2.x; a[5] += f2.y; a[6] += f3.x; a[7] += f3.y;
    }
    uint4 ov;
    *(__half2*)&ov.x = __floats2half2_rn(a[0], a[1]);
    *(__half2*)&ov.y = __floats2half2_rn(a[2], a[3]);
    *(__half2*)&ov.z = __floats2half2_rn(a[4], a[5]);
    *(__half2*)&ov.w = __floats2half2_rn(a[6], a[7]);
    *(uint4*)(cat + (size_t)ga * KCAT_P + 144 + lane * 8) = ov;
}

// ---------------------------------------------------------------------------
// Per-molecule self-attention (fp16 h input, 256-thread scores)
// ---------------------------------------------------------------------------
#define PAD 260
#define MOLATTN_SMEM ((2 * 32 * PAD + 32 * 32) * (int)sizeof(float))

__global__ void __launch_bounds__(256) mol_attn(
    const __half* __restrict__ atomh, const __half* __restrict__ hW,
    __half* __restrict__ t)
{
    extern __shared__ float sm[];
    float* sh = sm;
    float* sw = sm + 32 * PAD;
    float* sa = sm + 2 * 32 * PAD;

    const int b = blockIdx.x, tid = threadIdx.x;
    const __half* hb = atomh + (size_t)b * 32 * 256;
    const __half* wb = hW    + (size_t)b * 32 * 256;

    for (int i = tid; i < 32 * 256; i += 256) {
        const int a = i >> 8, k = i & 255;
        sh[a * PAD + k] = __half2float(hb[i]);
        sw[a * PAD + k] = __half2float(wb[i]);
    }
    __syncthreads();

    {
        const int a0 = (tid >> 4) * 2;
        const int c0 = (tid & 15) * 2;
        float acc[2][2] = {{0.f, 0.f}, {0.f, 0.f}};
        for (int k = 0; k < 256; k += 4) {
            float4 av0 = *(float4*)&sw[a0 * PAD + k];
            float4 av1 = *(float4*)&sw[(a0 + 1) * PAD + k];
            float4 bv0 = *(float4*)&sh[c0 * PAD + k];
            float4 bv1 = *(float4*)&sh[(c0 + 1) * PAD + k];
            acc[0][0] += av0.x * bv0.x + av0.y * bv0.y + av0.z * bv0.z + av0.w * bv0.w;
            acc[0][1] += av0.x * bv1.x + av0.y * bv1.y + av0.z * bv1.z + av0.w * bv1.w;
            acc[1][0] += av1.x * bv0.x + av1.y * bv0.y + av1.z * bv0.z + av1.w * bv0.w;
            acc[1][1] += av1.x * bv1.x + av1.y * bv1.y + av1.z * bv1.z + av1.w * bv1.w;
        }
        sa[a0 * 32 + c0]           = acc[0][0];
        sa[a0 * 32 + c0 + 1]       = acc[0][1];
        sa[(a0 + 1) * 32 + c0]     = acc[1][0];
        sa[(a0 + 1) * 32 + c0 + 1] = acc[1][1];
    }
    __syncthreads();

    const int wid = tid >> 5, lane = tid & 31;
    for (int a = wid; a < 32; a += 8) {
        float v = sa[a * 32 + lane];
        float m = v;
#pragma unroll
        for (int o = 16; o > 0; o >>= 1) m = fmaxf(m, __shfl_xor_sync(0xffffffffu, m, o));
        float ev = expf(v - m);
        float sum = ev;
#pragma unroll
        for (int o = 16; o > 0; o >>= 1) sum += __shfl_xor_sync(0xffffffffu, sum, o);
        sa[a * 32 + lane] = ev / sum;
    }
    __syncthreads();

    const int k = tid;
    float acc[32];
#pragma unroll
    for (int a = 0; a < 32; a++) acc[a] = 0.f;
    for (int c = 0; c < 32; c++) {
        const float hv = sh[c * PAD + k];
#pragma unroll
        for (int a = 0; a < 32; a++) acc[a] += sa[a * 32 + c] * hv;
    }
#pragma unroll
    for (int a = 0; a < 32; a++)
        t[((size_t)b * 32 + a) * 256 + k] = __float2half(acc[a]);
}

// out[b][k] = (sum_a h + attsum[b][k]) / 32
__global__ void __launch_bounds__(256) mol_reduce(
    const __half* __restrict__ atomh, const float* __restrict__ attsum,
    float* __restrict__ out)
{
    const int b = blockIdx.x, k = threadIdx.x;
    const __half* ph = atomh + (size_t)b * 32 * 256 + k;
    float s = attsum[(size_t)b * 256 + k];
#pragma unroll
    for (int a = 0; a < 32; a++) s += __half2float(ph[a * 256]);
    out[(size_t)b * 256 + k] = s * (1.0f / 32.0f);
}

// ---------------------------------------------------------------------------
extern "C" void kernel_launch(void* const* d_in, const int* in_sizes, int n_in,
                              void* d_out, int out_size)
{
    const float* fatoms = (const float*)d_in[0];
    const float* fbonds = (const float*)d_in[1];
    const int*   agraph = (const int*)d_in[2];
    const int*   bgraph = (const int*)d_in[3];
    const float* W_i    = (const float*)d_in[5];
    const float* W_h    = (const float*)d_in[6];
    const float* W_o_w  = (const float*)d_in[7];
    const float* W_o_b  = (const float*)d_in[8];
    const float* W_a    = (const float*)d_in[9];
    const float* W_b_w  = (const float*)d_in[10];
    const float* W_b_b  = (const float*)d_in[11];
    const float* W_ma1  = (const float*)d_in[12];
    float* out = (float*)d_out;

    float* scratch = nullptr;
    cudaGetSymbolAddress((void**)&scratch, g_scratch);
    float* p = scratch;
    __half* binput_h = (__half*)p;            p += EH / 2;
    __half* msg0     = (__half*)p;            p += EH / 2;
    __half* msg1     = (__half*)p;            p += EH / 2;
    __half* fbonds_h = (__half*)p;            p += (size_t)E_BONDS * KIN_P / 2;
    __half* cat      = (__half*)p;            p += (size_t)N_ATOMS_ * KCAT_P / 2;
    __half* atomh_h  = (__half*)p;            p += NH / 2;
    __half* tmp_h    = (__half*)p;            p += NH / 2;
    __half* tbuf     = (__half*)p;            p += NH / 2;
    float*  attsum   = p;                     p += (size_t)BMOL * 256;
    float*  scores0  = p;                     p += E_BONDS;
    float*  scores1  = p;                     p += E_BONDS;
    __half* Wall     = (__half*)p;
    __half* Wh_h = Wall;
    __half* Wa_h = Wh_h + HID * 256;
    __half* Wb_h = Wa_h + HID * 256;
    __half* Wi_p = Wb_h + HID * 256;
    __half* Wo_p = Wi_p + KIN_P * 256;

    cudaFuncSetAttribute(mol_attn, cudaFuncAttributeMaxDynamicSharedMemorySize,
                         MOLATTN_SMEM);
    cudaFuncSetAttribute(mp_step, cudaFuncAttributeMaxDynamicSharedMemorySize,
                         MP_SMEM);
    cudaFuncSetAttribute(hgemm<false,true,true,true,true,false>,
                         cudaFuncAttributeMaxDynamicSharedMemorySize, HG_SMEM);
    cudaFuncSetAttribute(hgemm<true,true,true,false,false,false>,
                         cudaFuncAttributeMaxDynamicSharedMemorySize, HG_SMEM);
    cudaFuncSetAttribute(hgemm<false,false,true,false,false,false>,
                         cudaFuncAttributeMaxDynamicSharedMemorySize, HG_SMEM);
    cudaFuncSetAttribute(hgemm<true,true,false,false,false,true>,
                         cudaFuncAttributeMaxDynamicSharedMemorySize, HG_SMEM);

    const dim3 gE(E_BONDS / 128, 2);
    const dim3 gN(N_ATOMS_ / 128, 2);

    // launch order puts G1 at profiled slot 4
    fb_conv<<<(E_BONDS * 20 + 255) / 256, 256>>>(fbonds, fbonds_h);
    build_wi<<<(KIN_P * 256 + 255) / 256, 256>>>(W_i, Wi_p);
    w2h_all<<<(3 * HID * 256 + 255) / 256, 256>>>(W_h, W_a, W_b_w, Wall,
                                                  scores0, E_BONDS);

    // G1: binput_h(raw) + msg0(relu) = fbonds_h @ Wi_p, fused scores0
    hgemm<false, true, true, true, true, false><<<gE, 256, HG_SMEM>>>(
        E_BONDS, KIN_P, fbonds_h, KIN_P, Wi_p, nullptr,
        msg0, binput_h, W_ma1, scores0, nullptr);

    build_wo<<<(KCAT_P * 256 + 255) / 256, 256>>>(W_o_w, Wo_p);

    // 3 fused message-passing steps
    mp_step<<<E_BONDS / 64, 256, MP_SMEM>>>(msg0, bgraph, scores0, Wh_h,
                                            binput_h, msg1, W_ma1, scores1);
    mp_step<<<E_BONDS / 64, 256, MP_SMEM>>>(msg1, bgraph, scores1, Wh_h,
                                            binput_h, msg0, W_ma1, scores0);
    mp_step<<<E_BONDS / 64, 256, MP_SMEM>>>(msg0, bgraph, scores0, Wh_h,
                                            binput_h, msg1, W_ma1, nullptr);

    // atom readout (fatoms conversion fused into the gather)
    atom_gather<<<N_ATOMS_ / 8, 256>>>(msg1, agraph, fatoms, cat);
    hgemm<true, true, true, false, false, false><<<gN, 256, HG_SMEM>>>(
        N_ATOMS_, KCAT_P, cat, KCAT_P, Wo_p, W_o_b,
        atomh_h, nullptr, nullptr, nullptr, nullptr);

    // molecule self-attention pooling
    hgemm<false, false, true, false, false, false><<<gN, 256, HG_SMEM>>>(
        N_ATOMS_, HID, atomh_h, HID, Wa_h, nullptr,
        tmp_h, nullptr, nullptr, nullptr, nullptr);               // hW
    mol_attn<<<BMOL, 256, MOLATTN_SMEM>>>(atomh_h, tmp_h, tbuf);  // t
    hgemm<true, true, false, false, false, true><<<gN, 256, HG_SMEM>>>(
        N_ATOMS_, HID, tbuf, HID, Wb_h, W_b_b,
        nullptr, nullptr, nullptr, nullptr, attsum);              // att_h sums
    mol_reduce<<<BMOL, 256>>>(atomh_h, attsum, out);
}

// round 16
// speedup vs baseline: 1.0555x; 1.0555x over previous
#include <cuda_runtime.h>
#include <cuda_fp16.h>
#include <cstdint>
#include <math.h>

#define E_BONDS   131072
#define N_ATOMS_  65536
#define HID       256
#define AFD       143
#define KIN       157
#define KIN_P     160
#define KCAT_P    416
#define BMOL      2048

#define EH  ((size_t)E_BONDS * HID)
#define NH  ((size_t)N_ATOMS_ * HID)
__device__ float g_scratch[127 * 1024 * 1024];

__device__ __forceinline__ uint32_t smem_u32(const void* p) {
    uint32_t a;
    asm("{ .reg .u64 t; cvta.to.shared.u64 t, %1; cvt.u32.u64 %0, t; }"
        : "=r"(a) : "l"(p));
    return a;
}
__device__ __forceinline__ void cp_async16(uint32_t dst, const void* src) {
    asm volatile("cp.async.cg.shared.global [%0], [%1], 16;"
                 :: "r"(dst), "l"(src));
}
#define CP_COMMIT() asm volatile("cp.async.commit_group;" ::: "memory")
#define CP_WAIT1()  asm volatile("cp.async.wait_group 1;" ::: "memory")
#define CP_WAIT2()  asm volatile("cp.async.wait_group 2;" ::: "memory")

// ---------------------------------------------------------------------------
// conversions / padding
// ---------------------------------------------------------------------------
__global__ void w2h_all(const float* __restrict__ s1, const float* __restrict__ s3,
                        const float* __restrict__ s4, __half* __restrict__ dst,
                        float* __restrict__ zbuf, int zn)
{
    int i = blockIdx.x * 256 + threadIdx.x;
    if (i < zn) zbuf[i] = 0.f;
    const int n1 = HID * 256, n3 = 2 * HID * 256, n4 = 3 * HID * 256;
    if (i >= n4) return;
    float v;
    if      (i < n1) v = s1[i];
    else if (i < n3) v = s3[i - n1];
    else             v = s4[i - n3];
    dst[i] = __float2half(v);
}

__global__ void build_wi(const float* __restrict__ W, __half* __restrict__ dst)
{
    int i = blockIdx.x * 256 + threadIdx.x;
    if (i >= KIN_P * 256) return;
    const int r = i >> 8;
    dst[i] = __float2half(r < KIN ? W[i] : 0.f);
}

__global__ void build_wo(const float* __restrict__ W, __half* __restrict__ dst)
{
    int i = blockIdx.x * 256 + threadIdx.x;
    if (i >= KCAT_P * 256) return;
    const int r = i >> 8, c = i & 255;
    float v = 0.f;
    if (r < 143)                  v = W[r * 256 + c];
    else if (r >= 144 && r < 400) v = W[(r - 1) * 256 + c];
    dst[i] = __float2half(v);
}

__global__ void fb_conv(const float* __restrict__ fb, __half* __restrict__ dst)
{
    int i = blockIdx.x * 256 + threadIdx.x;
    if (i >= E_BONDS * 20) return;
    const int e = i / 20, g = i - e * 20;
    const float* src = fb + (size_t)e * KIN + g * 8;
    __align__(16) __half hb[8];
#pragma unroll
    for (int k = 0; k < 8; k++) {
        const int c = g * 8 + k;
        hb[k] = __float2half(c < KIN ? src[k] : 0.f);
    }
    *(uint4*)&dst[(size_t)e * KIN_P + g * 8] = *(uint4*)hb;
}

// ---------------------------------------------------------------------------
// hgemm: 4-stage cp.async ring, K-chunk 32, block 128x128 (grid.y=2), fp16 A
// ATTSUM: per-molecule column sums of post-relu rows -> attsum[mol][col]
// ---------------------------------------------------------------------------
#define LDA_H 40
#define LDB_H 136
#define SA_EL (128 * LDA_H)
#define SB_EL (32 * LDB_H)
#define ST_EL (SA_EL + SB_EL)
#define HG_SMEM (4 * ST_EL * 2)

template<bool HAS_BIAS, bool RELU, bool OUTH, bool RAWH, bool SCOREF, bool ATTSUM>
__global__ void __launch_bounds__(256, 2) hgemm(
    int M, int K,
    const __half* __restrict__ Ah, int ldah,
    const __half* __restrict__ B,
    const float* __restrict__ bias,
    __half* __restrict__ outh,
    __half* __restrict__ rawh,
    const float* __restrict__ wma,
    float* __restrict__ scores_out,
    float* __restrict__ attsum)
{
    extern __shared__ __align__(16) __half smh[];

    const int tid  = threadIdx.x;
    const int wid  = tid >> 5;
    const int lane = tid & 31;
    const int m0   = blockIdx.x * 128;
    const int n0   = blockIdx.y * 128;
    const int wm   = (wid & 3) * 32;
    const int wn   = (wid >> 2) * 64;
    const int S    = K >> 5;

    float acc[2][8][4];
#pragma unroll
    for (int t = 0; t < 2; t++)
#pragma unroll
        for (int j = 0; j < 8; j++)
#pragma unroll
            for (int q = 0; q < 4; q++) acc[t][j][q] = 0.f;

    const int lrow = lane & 15;
    const int lcof = (lane >> 4) * 8;

    auto stage = [&](int s) {
        const int k0 = s * 32;
        __half* bA = smh + (s & 3) * ST_EL;
        __half* bB = bA + SA_EL;
#pragma unroll
        for (int it = 0; it < 2; it++) {
            const int id = tid + it * 256;
            const int r  = id >> 4;
            const int c8 = (id & 15) * 8;
            cp_async16(smem_u32(&bB[r * LDB_H + c8]),
                       &B[(size_t)(k0 + r) * 256 + n0 + c8]);
        }
#pragma unroll
        for (int it = 0; it < 2; it++) {
            const int id  = tid + it * 256;
            const int r   = id >> 2;
            const int c16 = (id & 3) * 8;
            cp_async16(smem_u32(&bA[r * LDA_H + c16]),
                       &Ah[(size_t)(m0 + r) * ldah + k0 + c16]);
        }
        CP_COMMIT();
    };

#pragma unroll
    for (int p = 0; p < 3; p++) {
        if (p < S) stage(p); else CP_COMMIT();
    }

    for (int s = 0; s < S; s++) {
        CP_WAIT2();
        __syncthreads();
        if (s + 3 < S) stage(s + 3); else CP_COMMIT();

        __half* bA = smh + (s & 3) * ST_EL;
        __half* bB = bA + SA_EL;
#pragma unroll
        for (int ks = 0; ks < 2; ks++) {
            uint32_t fa[2][4];
#pragma unroll
            for (int t = 0; t < 2; t++) {
                const uint32_t ad = smem_u32(&bA[(wm + t * 16 + lrow) * LDA_H + ks * 16 + lcof]);
                asm volatile("ldmatrix.sync.aligned.m8n8.x4.shared.b16 {%0,%1,%2,%3}, [%4];"
                             : "=r"(fa[t][0]), "=r"(fa[t][1]), "=r"(fa[t][2]), "=r"(fa[t][3])
                             : "r"(ad));
            }
            uint32_t fb[8][2];
#pragma unroll
            for (int nt = 0; nt < 4; nt++) {
                const uint32_t ad = smem_u32(&bB[(ks * 16 + lrow) * LDB_H + wn + nt * 16 + lcof]);
                uint32_t r0, r1, r2, r3;
                asm volatile("ldmatrix.sync.aligned.m8n8.x4.trans.shared.b16 {%0,%1,%2,%3}, [%4];"
                             : "=r"(r0), "=r"(r1), "=r"(r2), "=r"(r3) : "r"(ad));
                fb[nt * 2][0] = r0; fb[nt * 2][1] = r1;
                fb[nt * 2 + 1][0] = r2; fb[nt * 2 + 1][1] = r3;
            }
#pragma unroll
            for (int t = 0; t < 2; t++)
#pragma unroll
                for (int j = 0; j < 8; j++)
                    asm volatile(
                        "mma.sync.aligned.m16n8k16.row.col.f32.f16.f16.f32 "
                        "{%0,%1,%2,%3}, {%4,%5,%6,%7}, {%8,%9}, {%0,%1,%2,%3};"
                        : "+f"(acc[t][j][0]), "+f"(acc[t][j][1]),
                          "+f"(acc[t][j][2]), "+f"(acc[t][j][3])
                        : "r"(fa[t][0]), "r"(fa[t][1]), "r"(fa[t][2]), "r"(fa[t][3]),
                          "r"(fb[j][0]), "r"(fb[j][1]));
        }
    }

    float rowdot[2][2] = {{0.f, 0.f}, {0.f, 0.f}};
    float colsum[8][2];
    if (ATTSUM)
#pragma unroll
        for (int j = 0; j < 8; j++) { colsum[j][0] = 0.f; colsum[j][1] = 0.f; }

#pragma unroll
    for (int t = 0; t < 2; t++) {
        const int mrow = m0 + wm + t * 16 + (lane >> 2);
#pragma unroll
        for (int j = 0; j < 8; j++) {
            const int nc = n0 + wn + j * 8 + (lane & 3) * 2;
            float wx = 0.f, wy = 0.f;
            if (SCOREF) { wx = __ldg(&wma[nc]); wy = __ldg(&wma[nc + 1]); }
#pragma unroll
            for (int hf = 0; hf < 2; hf++) {
                const size_t m = (size_t)(mrow + hf * 8);
                float vx = acc[t][j][hf * 2 + 0];
                float vy = acc[t][j][hf * 2 + 1];
                if (HAS_BIAS) { vx += bias[nc]; vy += bias[nc + 1]; }
                if (RAWH) *(__half2*)&rawh[m * 256 + nc] = __floats2half2_rn(vx, vy);
                if (RELU) { vx = fmaxf(vx, 0.f); vy = fmaxf(vy, 0.f); }
                if (OUTH) *(__half2*)&outh[m * 256 + nc] = __floats2half2_rn(vx, vy);
                if (SCOREF) rowdot[t][hf] += vx * wx + vy * wy;
                if (ATTSUM) { colsum[j][0] += vx; colsum[j][1] += vy; }
            }
        }
    }
    if (SCOREF) {
#pragma unroll
        for (int t = 0; t < 2; t++)
#pragma unroll
            for (int hf = 0; hf < 2; hf++) {
                float v = rowdot[t][hf];
                v += __shfl_xor_sync(0xffffffffu, v, 1);
                v += __shfl_xor_sync(0xffffffffu, v, 2);
                if ((lane & 3) == 0)
                    atomicAdd(&scores_out[m0 + wm + t * 16 + hf * 8 + (lane >> 2)], v);
            }
    }
    if (ATTSUM) {
        const int mol = (m0 >> 5) + (wid & 3);   // warp-m tile = 1 molecule
#pragma unroll
        for (int j = 0; j < 8; j++) {
            float cx = colsum[j][0], cy = colsum[j][1];
#pragma unroll
            for (int o = 4; o <= 16; o <<= 1) {
                cx += __shfl_xor_sync(0xffffffffu, cx, o);
                cy += __shfl_xor_sync(0xffffffffu, cy, o);
            }
            if ((lane >> 2) == 0) {
                const int nc = n0 + wn + j * 8 + (lane & 3) * 2;
                *(float2*)&attsum[(size_t)mol * 256 + nc] = make_float2(cx, cy);
            }
        }
    }
}

// ---------------------------------------------------------------------------
// FUSED message-passing step (R14 proven config: 3-stage B ring, K-chunk 32)
// ---------------------------------------------------------------------------
#define MP_LDA 264
#define MP_LDB 264
#define MP_SA  (64 * MP_LDA)
#define MP_SB  (32 * MP_LDB)
#define MP_SMEM ((MP_SA + 3 * MP_SB) * 2)

__global__ void __launch_bounds__(256, 2) mp_step(
    const __half* __restrict__ msg, const int* __restrict__ bgraph,
    const float* __restrict__ scores, const __half* __restrict__ Wh,
    const __half* __restrict__ binput, __half* __restrict__ msg_out,
    const float* __restrict__ wma, float* __restrict__ scores_out)
{
    extern __shared__ __align__(16) __half smh[];
    __shared__ float sred[64];
    __half* sA = smh;
    __half* sBr = smh + MP_SA;

    const int tid  = threadIdx.x;
    const int wid  = tid >> 5;
    const int lane = tid & 31;
    const int e0   = blockIdx.x * 64;
    const int wm   = (wid & 1) * 32;
    const int wn   = (wid >> 1) * 64;

    if (tid < 64) sred[tid] = 0.f;

    auto stageB = [&](int s) {
        const int k0 = s * 32;
        __half* bB = sBr + (s % 3) * MP_SB;
#pragma unroll
        for (int it = 0; it < 4; it++) {
            const int id = tid + it * 256;
            const int r  = id >> 5;
            const int c8 = (id & 31) * 8;
            cp_async16(smem_u32(&bB[r * MP_LDB + c8]),
                       &Wh[(size_t)(k0 + r) * 256 + c8]);
        }
        CP_COMMIT();
    };

    stageB(0); stageB(1);

    // ---- gather: 2-row software pipeline ----
    {
        int   idxr[8];
        float scr[8];
#pragma unroll
        for (int rr = 0; rr < 8; rr++) {
            const int e = e0 + wid * 8 + rr;
            int id = 0; float sc = 0.f;
            if (lane < 6) {
                id = bgraph[e * 6 + lane];
                sc = __ldg(&scores[id]);
            }
            idxr[rr] = id; scr[rr] = sc;
        }
#pragma unroll
        for (int pr = 0; pr < 4; pr++) {
            const int r0 = pr * 2, r1 = pr * 2 + 1;
            int   nb0[6], nb1[6];
            float s0[6], s1[6];
#pragma unroll
            for (int j = 0; j < 6; j++) {
                nb0[j] = __shfl_sync(0xffffffffu, idxr[r0], j);
                s0[j]  = __shfl_sync(0xffffffffu, scr[r0], j);
                nb1[j] = __shfl_sync(0xffffffffu, idxr[r1], j);
                s1[j]  = __shfl_sync(0xffffffffu, scr[r1], j);
            }
            uint4 rv0[6], rv1[6];
#pragma unroll
            for (int j = 0; j < 6; j++)
                rv0[j] = *(const uint4*)(msg + (size_t)nb0[j] * 256 + lane * 8);
#pragma unroll
            for (int j = 0; j < 6; j++)
                rv1[j] = *(const uint4*)(msg + (size_t)nb1[j] * 256 + lane * 8);

            float w0[6], w1[6];
            {
                float mx0 = s0[0], mx1 = s1[0];
#pragma unroll
                for (int j = 1; j < 6; j++) { mx0 = fmaxf(mx0, s0[j]); mx1 = fmaxf(mx1, s1[j]); }
                float sum0 = 0.f, sum1 = 0.f;
#pragma unroll
                for (int j = 0; j < 6; j++) {
                    w0[j] = expf(s0[j] - mx0); sum0 += w0[j];
                    w1[j] = expf(s1[j] - mx1); sum1 += w1[j];
                }
                const float i0 = 1.0f / sum0, i1 = 1.0f / sum1;
#pragma unroll
                for (int j = 0; j < 6; j++) { w0[j] *= i0; w1[j] *= i1; }
            }

            float a0[8] = {0,0,0,0,0,0,0,0}, a1[8] = {0,0,0,0,0,0,0,0};
#pragma unroll
            for (int j = 0; j < 6; j++) {
                const float2 f0 = __half22float2(*(const __half2*)&rv0[j].x);
                const float2 f1 = __half22float2(*(const __half2*)&rv0[j].y);
                const float2 f2 = __half22float2(*(const __half2*)&rv0[j].z);
                const float2 f3 = __half22float2(*(const __half2*)&rv0[j].w);
                a0[0] += w0[j] * f0.x; a0[1] += w0[j] * f0.y;
                a0[2] += w0[j] * f1.x; a0[3] += w0[j] * f1.y;
                a0[4] += w0[j] * f2.x; a0[5] += w0[j] * f2.y;
                a0[6] += w0[j] * f3.x; a0[7] += w0[j] * f3.y;
            }
#pragma unroll
            for (int j = 0; j < 6; j++) {
                const float2 f0 = __half22float2(*(const __half2*)&rv1[j].x);
                const float2 f1 = __half22float2(*(const __half2*)&rv1[j].y);
                const float2 f2 = __half22float2(*(const __half2*)&rv1[j].z);
                const float2 f3 = __half22float2(*(const __half2*)&rv1[j].w);
                a1[0] += w1[j] * f0.x; a1[1] += w1[j] * f0.y;
                a1[2] += w1[j] * f1.x; a1[3] += w1[j] * f1.y;
                a1[4] += w1[j] * f2.x; a1[5] += w1[j] * f2.y;
                a1[6] += w1[j] * f3.x; a1[7] += w1[j] * f3.y;
            }
            uint4 ov;
            *(__half2*)&ov.x = __floats2half2_rn(a0[0], a0[1]);
            *(__half2*)&ov.y = __floats2half2_rn(a0[2], a0[3]);
            *(__half2*)&ov.z = __floats2half2_rn(a0[4], a0[5]);
            *(__half2*)&ov.w = __floats2half2_rn(a0[6], a0[7]);
            *(uint4*)&sA[(wid * 8 + r0) * MP_LDA + lane * 8] = ov;
            *(__half2*)&ov.x = __floats2half2_rn(a1[0], a1[1]);
            *(__half2*)&ov.y = __floats2half2_rn(a1[2], a1[3]);
            *(__half2*)&ov.z = __floats2half2_rn(a1[4], a1[5]);
            *(__half2*)&ov.w = __floats2half2_rn(a1[6], a1[7]);
            *(uint4*)&sA[(wid * 8 + r1) * MP_LDA + lane * 8] = ov;
        }
    }

    float acc[2][8][4];
#pragma unroll
    for (int t = 0; t < 2; t++)
#pragma unroll
        for (int j = 0; j < 8; j++)
#pragma unroll
            for (int q = 0; q < 4; q++) acc[t][j][q] = 0.f;

    const int lrow = lane & 15;
    const int lcof = (lane >> 4) * 8;

    for (int s = 0; s < 8; s++) {
        CP_WAIT1();
        __syncthreads();
        if (s + 2 < 8) stageB(s + 2); else CP_COMMIT();

        __half* bB = sBr + (s % 3) * MP_SB;
#pragma unroll
        for (int ks = 0; ks < 2; ks++) {
            const int kcol = s * 32 + ks * 16;
            uint32_t fa[2][4];
#pragma unroll
            for (int t = 0; t < 2; t++) {
                const uint32_t ad = smem_u32(&sA[(wm + t * 16 + lrow) * MP_LDA + kcol + lcof]);
                asm volatile("ldmatrix.sync.aligned.m8n8.x4.shared.b16 {%0,%1,%2,%3}, [%4];"
                             : "=r"(fa[t][0]), "=r"(fa[t][1]), "=r"(fa[t][2]), "=r"(fa[t][3])
                             : "r"(ad));
            }
            uint32_t fb[8][2];
#pragma unroll
            for (int nt = 0; nt < 4; nt++) {
                const uint32_t ad = smem_u32(&bB[(ks * 16 + lrow) * MP_LDB + wn + nt * 16 + lcof]);
                uint32_t r0, r1, r2, r3;
                asm volatile("ldmatrix.sync.aligned.m8n8.x4.trans.shared.b16 {%0,%1,%2,%3}, [%4];"
                             : "=r"(r0), "=r"(r1), "=r"(r2), "=r"(r3) : "r"(ad));
                fb[nt * 2][0] = r0; fb[nt * 2][1] = r1;
                fb[nt * 2 + 1][0] = r2; fb[nt * 2 + 1][1] = r3;
            }
#pragma unroll
            for (int t = 0; t < 2; t++)
#pragma unroll
                for (int j = 0; j < 8; j++)
                    asm volatile(
                        "mma.sync.aligned.m16n8k16.row.col.f32.f16.f16.f32 "
                        "{%0,%1,%2,%3}, {%4,%5,%6,%7}, {%8,%9}, {%0,%1,%2,%3};"
                        : "+f"(acc[t][j][0]), "+f"(acc[t][j][1]),
                          "+f"(acc[t][j][2]), "+f"(acc[t][j][3])
                        : "r"(fa[t][0]), "r"(fa[t][1]), "r"(fa[t][2]), "r"(fa[t][3]),
                          "r"(fb[j][0]), "r"(fb[j][1]));
        }
    }

    float rowdot[2][2] = {{0.f, 0.f}, {0.f, 0.f}};
#pragma unroll
    for (int t = 0; t < 2; t++) {
        const int mrow = e0 + wm + t * 16 + (lane >> 2);
#pragma unroll
        for (int j = 0; j < 8; j++) {
            const int nc = wn + j * 8 + (lane & 3) * 2;
            const float wx = __ldg(&wma[nc]);
            const float wy = __ldg(&wma[nc + 1]);
#pragma unroll
            for (int hf = 0; hf < 2; hf++) {
                const size_t m = (size_t)(mrow + hf * 8);
                float vx = acc[t][j][hf * 2 + 0];
                float vy = acc[t][j][hf * 2 + 1];
                const float2 d = __half22float2(*(const __half2*)&binput[m * 256 + nc]);
                vx = fmaxf(vx + d.x, 0.f);
                vy = fmaxf(vy + d.y, 0.f);
                *(__half2*)&msg_out[m * 256 + nc] = __floats2half2_rn(vx, vy);
                rowdot[t][hf] += vx * wx + vy * wy;
            }
        }
    }
    if (scores_out) {
#pragma unroll
        for (int t = 0; t < 2; t++)
#pragma unroll
            for (int hf = 0; hf < 2; hf++) {
                float v = rowdot[t][hf];
                v += __shfl_xor_sync(0xffffffffu, v, 1);
                v += __shfl_xor_sync(0xffffffffu, v, 2);
                if ((lane & 3) == 0)
                    atomicAdd(&sred[wm + t * 16 + hf * 8 + (lane >> 2)], v);
            }
        __syncthreads();
        if (tid < 64) scores_out[e0 + tid] = sred[tid];
    }
}

// ---------------------------------------------------------------------------
// atom_gather + fused fatoms conversion
// ---------------------------------------------------------------------------
__global__ void __launch_bounds__(256) atom_gather(
    const __half* __restrict__ msg, const int* __restrict__ agraph,
    const float* __restrict__ fa, __half* __restrict__ cat)
{
    const int ga   = (blockIdx.x * 256 + threadIdx.x) >> 5;
    const int lane = threadIdx.x & 31;
    if (ga >= N_ATOMS_) return;

    if (lane < 18) {
        const float* src = fa + (size_t)ga * AFD + lane * 8;
        __align__(16) __half hb[8];
#pragma unroll
        for (int k = 0; k < 8; k++) {
            const int c = lane * 8 + k;
            hb[k] = __float2half(c < AFD ? src[k] : 0.f);
        }
        *(uint4*)&cat[(size_t)ga * KCAT_P + lane * 8] = *(uint4*)hb;
    } else if (lane < 20) {
        uint4 z = make_uint4(0, 0, 0, 0);
        *(uint4*)&cat[(size_t)ga * KCAT_P + 400 + (lane - 18) * 8] = z;
    }

    float a[8] = {0, 0, 0, 0, 0, 0, 0, 0};
#pragma unroll
    for (int j = 0; j < 6; j++) {
        const int nb = agraph[ga * 6 + j];
        const uint4 rv = *(const uint4*)(msg + (size_t)nb * 256 + lane * 8);
        const float2 f0 = __half22float2(*(const __half2*)&rv.x);
        const float2 f1 = __half22float2(*(const __half2*)&rv.y);
        const float2 f2 = __half22float2(*(const __half2*)&rv.z);
        const float2 f3 = __half22float2(*(const __half2*)&rv.w);
        a[0] += f0.x; a[1] += f0.y; a[2] += f1.x; a[3] += f1.y;
        a[4] += f2.x; a[5] += f2.y; a[6] += f3.x; a[7] += f3.y;
    }
    uint4 ov;
    *(__half2*)&ov.x = __floats2half2_rn(a[0], a[1]);
    *(__half2*)&ov.y = __floats2half2_rn(a[2], a[3]);
    *(__half2*)&ov.z = __floats2half2_rn(a[4], a[5]);
    *(__half2*)&ov.w = __floats2half2_rn(a[6], a[7]);
    *(uint4*)(cat + (size_t)ga * KCAT_P + 144 + lane * 8) = ov;
}

// ---------------------------------------------------------------------------
// Per-molecule self-attention (fp16 h input, 256-thread scores)
// ---------------------------------------------------------------------------
#define PAD 260
#define MOLATTN_SMEM ((2 * 32 * PAD + 32 * 32) * (int)sizeof(float))

__global__ void __launch_bounds__(256) mol_attn(
    const __half* __restrict__ atomh, const __half* __restrict__ hW,
    __half* __restrict__ t)
{
    extern __shared__ float sm[];
    float* sh = sm;
    float* sw = sm + 32 * PAD;
    float* sa = sm + 2 * 32 * PAD;

    const int b = blockIdx.x, tid = threadIdx.x;
    const __half* hb = atomh + (size_t)b * 32 * 256;
    const __half* wb = hW    + (size_t)b * 32 * 256;

    for (int i = tid; i < 32 * 256; i += 256) {
        const int a = i >> 8, k = i & 255;
        sh[a * PAD + k] = __half2float(hb[i]);
        sw[a * PAD + k] = __half2float(wb[i]);
    }
    __syncthreads();

    {
        const int a0 = (tid >> 4) * 2;
        const int c0 = (tid & 15) * 2;
        float acc[2][2] = {{0.f, 0.f}, {0.f, 0.f}};
        for (int k = 0; k < 256; k += 4) {
            float4 av0 = *(float4*)&sw[a0 * PAD + k];
            float4 av1 = *(float4*)&sw[(a0 + 1) * PAD + k];
            float4 bv0 = *(float4*)&sh[c0 * PAD + k];
            float4 bv1 = *(float4*)&sh[(c0 + 1) * PAD + k];
            acc[0][0] += av0.x * bv0.x + av0.y * bv0.y + av0.z * bv0.z + av0.w * bv0.w;
            acc[0][1] += av0.x * bv1.x + av0.y * bv1.y + av0.z * bv1.z + av0.w * bv1.w;
            acc[1][0] += av1.x * bv0.x + av1.y * bv0.y + av1.z * bv0.z + av1.w * bv0.w;
            acc[1][1] += av1.x * bv1.x + av1.y * bv1.y + av1.z * bv1.z + av1.w * bv1.w;
        }
        sa[a0 * 32 + c0]           = acc[0][0];
        sa[a0 * 32 + c0 + 1]       = acc[0][1];
        sa[(a0 + 1) * 32 + c0]     = acc[1][0];
        sa[(a0 + 1) * 32 + c0 + 1] = acc[1][1];
    }
    __syncthreads();

    const int wid = tid >> 5, lane = tid & 31;
    for (int a = wid; a < 32; a += 8) {
        float v = sa[a * 32 + lane];
        float m = v;
#pragma unroll
        for (int o = 16; o > 0; o >>= 1) m = fmaxf(m, __shfl_xor_sync(0xffffffffu, m, o));
        float ev = expf(v - m);
        float sum = ev;
#pragma unroll
        for (int o = 16; o > 0; o >>= 1) sum += __shfl_xor_sync(0xffffffffu, sum, o);
        sa[a * 32 + lane] = ev / sum;
    }
    __syncthreads();

    const int k = tid;
    float acc[32];
#pragma unroll
    for (int a = 0; a < 32; a++) acc[a] = 0.f;
    for (int c = 0; c < 32; c++) {
        const float hv = sh[c * PAD + k];
#pragma unroll
        for (int a = 0; a < 32; a++) acc[a] += sa[a * 32 + c] * hv;
    }
#pragma unroll
    for (int a = 0; a < 32; a++)
        t[((size_t)b * 32 + a) * 256 + k] = __float2half(acc[a]);
}

// out[b][k] = (sum_a h + attsum[b][k]) / 32
__global__ void __launch_bounds__(256) mol_reduce(
    const __half* __restrict__ atomh, const float* __restrict__ attsum,
    float* __restrict__ out)
{
    const int b = blockIdx.x, k = threadIdx.x;
    const __half* ph = atomh + (size_t)b * 32 * 256 + k;
    float s = attsum[(size_t)b * 256 + k];
#pragma unroll
    for (int a = 0; a < 32; a++) s += __half2float(ph[a * 256]);
    out[(size_t)b * 256 + k] = s * (1.0f / 32.0f);
}

// ---------------------------------------------------------------------------
extern "C" void kernel_launch(void* const* d_in, const int* in_sizes, int n_in,
                              void* d_out, int out_size)
{
    const float* fatoms = (const float*)d_in[0];
    const float* fbonds = (const float*)d_in[1];
    const int*   agraph = (const int*)d_in[2];
    const int*   bgraph = (const int*)d_in[3];
    const float* W_i    = (const float*)d_in[5];
    const float* W_h    = (const float*)d_in[6];
    const float* W_o_w  = (const float*)d_in[7];
    const float* W_o_b  = (const float*)d_in[8];
    const float* W_a    = (const float*)d_in[9];
    const float* W_b_w  = (const float*)d_in[10];
    const float* W_b_b  = (const float*)d_in[11];
    const float* W_ma1  = (const float*)d_in[12];
    float* out = (float*)d_out;

    float* scratch = nullptr;
    cudaGetSymbolAddress((void**)&scratch, g_scratch);
    float* p = scratch;
    __half* binput_h = (__half*)p;            p += EH / 2;
    __half* msg0     = (__half*)p;            p += EH / 2;
    __half* msg1     = (__half*)p;            p += EH / 2;
    __half* fbonds_h = (__half*)p;            p += (size_t)E_BONDS * KIN_P / 2;
    __half* cat      = (__half*)p;            p += (size_t)N_ATOMS_ * KCAT_P / 2;
    __half* atomh_h  = (__half*)p;            p += NH / 2;
    __half* tmp_h    = (__half*)p;            p += NH / 2;
    __half* tbuf     = (__half*)p;            p += NH / 2;
    float*  attsum   = p;                     p += (size_t)BMOL * 256;
    float*  scores0  = p;                     p += E_BONDS;
    float*  scores1  = p;                     p += E_BONDS;
    __half* Wall     = (__half*)p;
    __half* Wh_h = Wall;
    __half* Wa_h = Wh_h + HID * 256;
    __half* Wb_h = Wa_h + HID * 256;
    __half* Wi_p = Wb_h + HID * 256;
    __half* Wo_p = Wi_p + KIN_P * 256;

    cudaFuncSetAttribute(mol_attn, cudaFuncAttributeMaxDynamicSharedMemorySize,
                         MOLATTN_SMEM);
    cudaFuncSetAttribute(mp_step, cudaFuncAttributeMaxDynamicSharedMemorySize,
                         MP_SMEM);
    cudaFuncSetAttribute(hgemm<false,true,true,true,true,false>,
                         cudaFuncAttributeMaxDynamicSharedMemorySize, HG_SMEM);
    cudaFuncSetAttribute(hgemm<true,true,true,false,false,false>,
                         cudaFuncAttributeMaxDynamicSharedMemorySize, HG_SMEM);
    cudaFuncSetAttribute(hgemm<false,false,true,false,false,false>,
                         cudaFuncAttributeMaxDynamicSharedMemorySize, HG_SMEM);
    cudaFuncSetAttribute(hgemm<true,true,false,false,false,true>,
                         cudaFuncAttributeMaxDynamicSharedMemorySize, HG_SMEM);

    const dim3 gE(E_BONDS / 128, 2);
    const dim3 gN(N_ATOMS_ / 128, 2);

    fb_conv<<<(E_BONDS * 20 + 255) / 256, 256>>>(fbonds, fbonds_h);
    build_wi<<<(KIN_P * 256 + 255) / 256, 256>>>(W_i, Wi_p);
    w2h_all<<<(3 * HID * 256 + 255) / 256, 256>>>(W_h, W_a, W_b_w, Wall,
                                                  scores0, E_BONDS);

    // G1: binput_h(raw) + msg0(relu) = fbonds_h @ Wi_p, fused scores0
    hgemm<false, true, true, true, true, false><<<gE, 256, HG_SMEM>>>(
        E_BONDS, KIN_P, fbonds_h, KIN_P, Wi_p, nullptr,
        msg0, binput_h, W_ma1, scores0, nullptr);

    build_wo<<<(KCAT_P * 256 + 255) / 256, 256>>>(W_o_w, Wo_p);

    // 3 fused message-passing steps
    mp_step<<<E_BONDS / 64, 256, MP_SMEM>>>(msg0, bgraph, scores0, Wh_h,
                                            binput_h, msg1, W_ma1, scores1);
    mp_step<<<E_BONDS / 64, 256, MP_SMEM>>>(msg1, bgraph, scores1, Wh_h,
                                            binput_h, msg0, W_ma1, scores0);
    mp_step<<<E_BONDS / 64, 256, MP_SMEM>>>(msg0, bgraph, scores0, Wh_h,
                                            binput_h, msg1, W_ma1, nullptr);

    // atom readout (fatoms conversion fused into the gather)
    atom_gather<<<N_ATOMS_ / 8, 256>>>(msg1, agraph, fatoms, cat);
    hgemm<true, true, true, false, false, false><<<gN, 256, HG_SMEM>>>(
        N_ATOMS_, KCAT_P, cat, KCAT_P, Wo_p, W_o_b,
        atomh_h, nullptr, nullptr, nullptr, nullptr);

    // molecule self-attention pooling
    hgemm<false, false, true, false, false, false><<<gN, 256, HG_SMEM>>>(
        N_ATOMS_, HID, atomh_h, HID, Wa_h, nullptr,
        tmp_h, nullptr, nullptr, nullptr, nullptr);               // hW
    mol_attn<<<BMOL, 256, MOLATTN_SMEM>>>(atomh_h, tmp_h, tbuf);  // t
    hgemm<true, true, false, false, false, true><<<gN, 256, HG_SMEM>>>(
        N_ATOMS_, HID, tbuf, HID, Wb_h, W_b_b,
        nullptr, nullptr, nullptr, nullptr, attsum);              // att_h sums
    mol_reduce<<<BMOL, 256>>>(atomh_h, attsum, out);
}

// round 17
// speedup vs baseline: 1.1493x; 1.0889x over previous
#include <cuda_runtime.h>
#include <cuda_fp16.h>
#include <cstdint>
#include <math.h>

#define E_BONDS   131072
#define N_ATOMS_  65536
#define HID       256
#define AFD       143
#define KIN       157
#define KIN_P     160
#define KCAT_P    416
#define BMOL      2048

#define EH  ((size_t)E_BONDS * HID)
#define NH  ((size_t)N_ATOMS_ * HID)
__device__ float g_scratch[127 * 1024 * 1024];

__device__ __forceinline__ uint32_t smem_u32(const void* p) {
    uint32_t a;
    asm("{ .reg .u64 t; cvta.to.shared.u64 t, %1; cvt.u32.u64 %0, t; }"
        : "=r"(a) : "l"(p));
    return a;
}
__device__ __forceinline__ void cp_async16(uint32_t dst, const void* src) {
    asm volatile("cp.async.cg.shared.global [%0], [%1], 16;"
                 :: "r"(dst), "l"(src));
}
#define CP_COMMIT() asm volatile("cp.async.commit_group;" ::: "memory")
#define CP_WAIT1()  asm volatile("cp.async.wait_group 1;" ::: "memory")
#define CP_WAIT2()  asm volatile("cp.async.wait_group 2;" ::: "memory")

// ---------------------------------------------------------------------------
// conversions / padding
// ---------------------------------------------------------------------------
__global__ void w2h_all(const float* __restrict__ wh, __half* __restrict__ dst,
                        float* __restrict__ zbuf, int zn)
{
    int i = blockIdx.x * 256 + threadIdx.x;
    if (i < zn) zbuf[i] = 0.f;
    if (i >= HID * 256) return;
    dst[i] = __float2half(wh[i]);
}

// Wab[k][512]: cols 0..255 = Wa[k], 256..511 = Wb[k]
__global__ void build_wab(const float* __restrict__ Wa, const float* __restrict__ Wb,
                          __half* __restrict__ dst)
{
    int i = blockIdx.x * 256 + threadIdx.x;
    if (i >= HID * 512) return;
    const int k = i >> 9, c = i & 511;
    dst[i] = __float2half(c < 256 ? Wa[k * 256 + c] : Wb[k * 256 + (c - 256)]);
}

__global__ void build_wi(const float* __restrict__ W, __half* __restrict__ dst)
{
    int i = blockIdx.x * 256 + threadIdx.x;
    if (i >= KIN_P * 256) return;
    const int r = i >> 8;
    dst[i] = __float2half(r < KIN ? W[i] : 0.f);
}

__global__ void build_wo(const float* __restrict__ W, __half* __restrict__ dst)
{
    int i = blockIdx.x * 256 + threadIdx.x;
    if (i >= KCAT_P * 256) return;
    const int r = i >> 8, c = i & 255;
    float v = 0.f;
    if (r < 143)                  v = W[r * 256 + c];
    else if (r >= 144 && r < 400) v = W[(r - 1) * 256 + c];
    dst[i] = __float2half(v);
}

__global__ void fb_conv(const float* __restrict__ fb, __half* __restrict__ dst)
{
    int i = blockIdx.x * 256 + threadIdx.x;
    if (i >= E_BONDS * 20) return;
    const int e = i / 20, g = i - e * 20;
    const float* src = fb + (size_t)e * KIN + g * 8;
    __align__(16) __half hb[8];
#pragma unroll
    for (int k = 0; k < 8; k++) {
        const int c = g * 8 + k;
        hb[k] = __float2half(c < KIN ? src[k] : 0.f);
    }
    *(uint4*)&dst[(size_t)e * KIN_P + g * 8] = *(uint4*)hb;
}

// ---------------------------------------------------------------------------
// hgemm: 4-stage cp.async ring, K-chunk 32, block 128x128, fp16 A
// N covered by grid.y (ldb/ldout parametric for the fused Wab GEMM)
// ---------------------------------------------------------------------------
#define LDA_H 40
#define LDB_H 136
#define SA_EL (128 * LDA_H)
#define SB_EL (32 * LDB_H)
#define ST_EL (SA_EL + SB_EL)
#define HG_SMEM (4 * ST_EL * 2)

template<bool HAS_BIAS, bool RELU, bool OUTH, bool RAWH, bool SCOREF>
__global__ void __launch_bounds__(256, 2) hgemm(
    int M, int K,
    const __half* __restrict__ Ah, int ldah,
    const __half* __restrict__ B, int ldb,
    const float* __restrict__ bias,
    __half* __restrict__ outh, int ldout,
    __half* __restrict__ rawh,
    const float* __restrict__ wma,
    float* __restrict__ scores_out)
{
    extern __shared__ __align__(16) __half smh[];

    const int tid  = threadIdx.x;
    const int wid  = tid >> 5;
    const int lane = tid & 31;
    const int m0   = blockIdx.x * 128;
    const int n0   = blockIdx.y * 128;
    const int wm   = (wid & 3) * 32;
    const int wn   = (wid >> 2) * 64;
    const int S    = K >> 5;

    float acc[2][8][4];
#pragma unroll
    for (int t = 0; t < 2; t++)
#pragma unroll
        for (int j = 0; j < 8; j++)
#pragma unroll
            for (int q = 0; q < 4; q++) acc[t][j][q] = 0.f;

    const int lrow = lane & 15;
    const int lcof = (lane >> 4) * 8;

    auto stage = [&](int s) {
        const int k0 = s * 32;
        __half* bA = smh + (s & 3) * ST_EL;
        __half* bB = bA + SA_EL;
#pragma unroll
        for (int it = 0; it < 2; it++) {
            const int id = tid + it * 256;
            const int r  = id >> 4;
            const int c8 = (id & 15) * 8;
            cp_async16(smem_u32(&bB[r * LDB_H + c8]),
                       &B[(size_t)(k0 + r) * ldb + n0 + c8]);
        }
#pragma unroll
        for (int it = 0; it < 2; it++) {
            const int id  = tid + it * 256;
            const int r   = id >> 2;
            const int c16 = (id & 3) * 8;
            cp_async16(smem_u32(&bA[r * LDA_H + c16]),
                       &Ah[(size_t)(m0 + r) * ldah + k0 + c16]);
        }
        CP_COMMIT();
    };

#pragma unroll
    for (int p = 0; p < 3; p++) {
        if (p < S) stage(p); else CP_COMMIT();
    }

    for (int s = 0; s < S; s++) {
        CP_WAIT2();
        __syncthreads();
        if (s + 3 < S) stage(s + 3); else CP_COMMIT();

        __half* bA = smh + (s & 3) * ST_EL;
        __half* bB = bA + SA_EL;
#pragma unroll
        for (int ks = 0; ks < 2; ks++) {
            uint32_t fa[2][4];
#pragma unroll
            for (int t = 0; t < 2; t++) {
                const uint32_t ad = smem_u32(&bA[(wm + t * 16 + lrow) * LDA_H + ks * 16 + lcof]);
                asm volatile("ldmatrix.sync.aligned.m8n8.x4.shared.b16 {%0,%1,%2,%3}, [%4];"
                             : "=r"(fa[t][0]), "=r"(fa[t][1]), "=r"(fa[t][2]), "=r"(fa[t][3])
                             : "r"(ad));
            }
            uint32_t fb[8][2];
#pragma unroll
            for (int nt = 0; nt < 4; nt++) {
                const uint32_t ad = smem_u32(&bB[(ks * 16 + lrow) * LDB_H + wn + nt * 16 + lcof]);
                uint32_t r0, r1, r2, r3;
                asm volatile("ldmatrix.sync.aligned.m8n8.x4.trans.shared.b16 {%0,%1,%2,%3}, [%4];"
                             : "=r"(r0), "=r"(r1), "=r"(r2), "=r"(r3) : "r"(ad));
                fb[nt * 2][0] = r0; fb[nt * 2][1] = r1;
                fb[nt * 2 + 1][0] = r2; fb[nt * 2 + 1][1] = r3;
            }
#pragma unroll
            for (int t = 0; t < 2; t++)
#pragma unroll
                for (int j = 0; j < 8; j++)
                    asm volatile(
                        "mma.sync.aligned.m16n8k16.row.col.f32.f16.f16.f32 "
                        "{%0,%1,%2,%3}, {%4,%5,%6,%7}, {%8,%9}, {%0,%1,%2,%3};"
                        : "+f"(acc[t][j][0]), "+f"(acc[t][j][1]),
                          "+f"(acc[t][j][2]), "+f"(acc[t][j][3])
                        : "r"(fa[t][0]), "r"(fa[t][1]), "r"(fa[t][2]), "r"(fa[t][3]),
                          "r"(fb[j][0]), "r"(fb[j][1]));
        }
    }

    float rowdot[2][2] = {{0.f, 0.f}, {0.f, 0.f}};
#pragma unroll
    for (int t = 0; t < 2; t++) {
        const int mrow = m0 + wm + t * 16 + (lane >> 2);
#pragma unroll
        for (int j = 0; j < 8; j++) {
            const int nc = n0 + wn + j * 8 + (lane & 3) * 2;
            float wx = 0.f, wy = 0.f;
            if (SCOREF) { wx = __ldg(&wma[nc]); wy = __ldg(&wma[nc + 1]); }
#pragma unroll
            for (int hf = 0; hf < 2; hf++) {
                const size_t m = (size_t)(mrow + hf * 8);
                float vx = acc[t][j][hf * 2 + 0];
                float vy = acc[t][j][hf * 2 + 1];
                if (HAS_BIAS) { vx += bias[nc]; vy += bias[nc + 1]; }
                if (RAWH) *(__half2*)&rawh[m * 256 + nc] = __floats2half2_rn(vx, vy);
                if (RELU) { vx = fmaxf(vx, 0.f); vy = fmaxf(vy, 0.f); }
                if (OUTH) *(__half2*)&outh[m * (size_t)ldout + nc] = __floats2half2_rn(vx, vy);
                if (SCOREF) rowdot[t][hf] += vx * wx + vy * wy;
            }
        }
    }
    if (SCOREF) {
#pragma unroll
        for (int t = 0; t < 2; t++)
#pragma unroll
            for (int hf = 0; hf < 2; hf++) {
                float v = rowdot[t][hf];
                v += __shfl_xor_sync(0xffffffffu, v, 1);
                v += __shfl_xor_sync(0xffffffffu, v, 2);
                if ((lane & 3) == 0)
                    atomicAdd(&scores_out[m0 + wm + t * 16 + hf * 8 + (lane >> 2)], v);
            }
    }
}

// ---------------------------------------------------------------------------
// FUSED message-passing step (R14 proven config). GRELU: relu gathered values.
// ---------------------------------------------------------------------------
#define MP_LDA 264
#define MP_LDB 264
#define MP_SA  (64 * MP_LDA)
#define MP_SB  (32 * MP_LDB)
#define MP_SMEM ((MP_SA + 3 * MP_SB) * 2)

template<bool GRELU>
__global__ void __launch_bounds__(256, 2) mp_step(
    const __half* __restrict__ msg, const int* __restrict__ bgraph,
    const float* __restrict__ scores, const __half* __restrict__ Wh,
    const __half* __restrict__ binput, __half* __restrict__ msg_out,
    const float* __restrict__ wma, float* __restrict__ scores_out)
{
    extern __shared__ __align__(16) __half smh[];
    __shared__ float sred[64];
    __half* sA = smh;
    __half* sBr = smh + MP_SA;

    const int tid  = threadIdx.x;
    const int wid  = tid >> 5;
    const int lane = tid & 31;
    const int e0   = blockIdx.x * 64;
    const int wm   = (wid & 1) * 32;
    const int wn   = (wid >> 1) * 64;

    if (tid < 64) sred[tid] = 0.f;

    auto stageB = [&](int s) {
        const int k0 = s * 32;
        __half* bB = sBr + (s % 3) * MP_SB;
#pragma unroll
        for (int it = 0; it < 4; it++) {
            const int id = tid + it * 256;
            const int r  = id >> 5;
            const int c8 = (id & 31) * 8;
            cp_async16(smem_u32(&bB[r * MP_LDB + c8]),
                       &Wh[(size_t)(k0 + r) * 256 + c8]);
        }
        CP_COMMIT();
    };

    stageB(0); stageB(1);

    // ---- gather: 2-row software pipeline ----
    {
        int   idxr[8];
        float scr[8];
#pragma unroll
        for (int rr = 0; rr < 8; rr++) {
            const int e = e0 + wid * 8 + rr;
            int id = 0; float sc = 0.f;
            if (lane < 6) {
                id = bgraph[e * 6 + lane];
                sc = __ldg(&scores[id]);
            }
            idxr[rr] = id; scr[rr] = sc;
        }
#pragma unroll
        for (int pr = 0; pr < 4; pr++) {
            const int r0 = pr * 2, r1 = pr * 2 + 1;
            int   nb0[6], nb1[6];
            float s0[6], s1[6];
#pragma unroll
            for (int j = 0; j < 6; j++) {
                nb0[j] = __shfl_sync(0xffffffffu, idxr[r0], j);
                s0[j]  = __shfl_sync(0xffffffffu, scr[r0], j);
                nb1[j] = __shfl_sync(0xffffffffu, idxr[r1], j);
                s1[j]  = __shfl_sync(0xffffffffu, scr[r1], j);
            }
            uint4 rv0[6], rv1[6];
#pragma unroll
            for (int j = 0; j < 6; j++)
                rv0[j] = *(const uint4*)(msg + (size_t)nb0[j] * 256 + lane * 8);
#pragma unroll
            for (int j = 0; j < 6; j++)
                rv1[j] = *(const uint4*)(msg + (size_t)nb1[j] * 256 + lane * 8);

            float w0[6], w1[6];
            {
                float mx0 = s0[0], mx1 = s1[0];
#pragma unroll
                for (int j = 1; j < 6; j++) { mx0 = fmaxf(mx0, s0[j]); mx1 = fmaxf(mx1, s1[j]); }
                float sum0 = 0.f, sum1 = 0.f;
#pragma unroll
                for (int j = 0; j < 6; j++) {
                    w0[j] = expf(s0[j] - mx0); sum0 += w0[j];
                    w1[j] = expf(s1[j] - mx1); sum1 += w1[j];
                }
                const float i0 = 1.0f / sum0, i1 = 1.0f / sum1;
#pragma unroll
                for (int j = 0; j < 6; j++) { w0[j] *= i0; w1[j] *= i1; }
            }

            float a0[8] = {0,0,0,0,0,0,0,0}, a1[8] = {0,0,0,0,0,0,0,0};
#pragma unroll
            for (int j = 0; j < 6; j++) {
                float2 f0 = __half22float2(*(const __half2*)&rv0[j].x);
                float2 f1 = __half22float2(*(const __half2*)&rv0[j].y);
                float2 f2 = __half22float2(*(const __half2*)&rv0[j].z);
                float2 f3 = __half22float2(*(const __half2*)&rv0[j].w);
                if (GRELU) {
                    f0.x = fmaxf(f0.x, 0.f); f0.y = fmaxf(f0.y, 0.f);
                    f1.x = fmaxf(f1.x, 0.f); f1.y = fmaxf(f1.y, 0.f);
                    f2.x = fmaxf(f2.x, 0.f); f2.y = fmaxf(f2.y, 0.f);
                    f3.x = fmaxf(f3.x, 0.f); f3.y = fmaxf(f3.y, 0.f);
                }
                a0[0] += w0[j] * f0.x; a0[1] += w0[j] * f0.y;
                a0[2] += w0[j] * f1.x; a0[3] += w0[j] * f1.y;
                a0[4] += w0[j] * f2.x; a0[5] += w0[j] * f2.y;
                a0[6] += w0[j] * f3.x; a0[7] += w0[j] * f3.y;
            }
#pragma unroll
            for (int j = 0; j < 6; j++) {
                float2 f0 = __half22float2(*(const __half2*)&rv1[j].x);
                float2 f1 = __half22float2(*(const __half2*)&rv1[j].y);
                float2 f2 = __half22float2(*(const __half2*)&rv1[j].z);
                float2 f3 = __half22float2(*(const __half2*)&rv1[j].w);
                if (GRELU) {
                    f0.x = fmaxf(f0.x, 0.f); f0.y = fmaxf(f0.y, 0.f);
                    f1.x = fmaxf(f1.x, 0.f); f1.y = fmaxf(f1.y, 0.f);
                    f2.x = fmaxf(f2.x, 0.f); f2.y = fmaxf(f2.y, 0.f);
                    f3.x = fmaxf(f3.x, 0.f); f3.y = fmaxf(f3.y, 0.f);
                }
                a1[0] += w1[j] * f0.x; a1[1] += w1[j] * f0.y;
                a1[2] += w1[j] * f1.x; a1[3] += w1[j] * f1.y;
                a1[4] += w1[j] * f2.x; a1[5] += w1[j] * f2.y;
                a1[6] += w1[j] * f3.x; a1[7] += w1[j] * f3.y;
            }
            uint4 ov;
            *(__half2*)&ov.x = __floats2half2_rn(a0[0], a0[1]);
            *(__half2*)&ov.y = __floats2half2_rn(a0[2], a0[3]);
            *(__half2*)&ov.z = __floats2half2_rn(a0[4], a0[5]);
            *(__half2*)&ov.w = __floats2half2_rn(a0[6], a0[7]);
            *(uint4*)&sA[(wid * 8 + r0) * MP_LDA + lane * 8] = ov;
            *(__half2*)&ov.x = __floats2half2_rn(a1[0], a1[1]);
            *(__half2*)&ov.y = __floats2half2_rn(a1[2], a1[3]);
            *(__half2*)&ov.z = __floats2half2_rn(a1[4], a1[5]);
            *(__half2*)&ov.w = __floats2half2_rn(a1[6], a1[7]);
            *(uint4*)&sA[(wid * 8 + r1) * MP_LDA + lane * 8] = ov;
        }
    }

    float acc[2][8][4];
#pragma unroll
    for (int t = 0; t < 2; t++)
#pragma unroll
        for (int j = 0; j < 8; j++)
#pragma unroll
            for (int q = 0; q < 4; q++) acc[t][j][q] = 0.f;

    const int lrow = lane & 15;
    const int lcof = (lane >> 4) * 8;

    for (int s = 0; s < 8; s++) {
        CP_WAIT1();
        __syncthreads();
        if (s + 2 < 8) stageB(s + 2); else CP_COMMIT();

        __half* bB = sBr + (s % 3) * MP_SB;
#pragma unroll
        for (int ks = 0; ks < 2; ks++) {
            const int kcol = s * 32 + ks * 16;
            uint32_t fa[2][4];
#pragma unroll
            for (int t = 0; t < 2; t++) {
                const uint32_t ad = smem_u32(&sA[(wm + t * 16 + lrow) * MP_LDA + kcol + lcof]);
                asm volatile("ldmatrix.sync.aligned.m8n8.x4.shared.b16 {%0,%1,%2,%3}, [%4];"
                             : "=r"(fa[t][0]), "=r"(fa[t][1]), "=r"(fa[t][2]), "=r"(fa[t][3])
                             : "r"(ad));
            }
            uint32_t fb[8][2];
#pragma unroll
            for (int nt = 0; nt < 4; nt++) {
                const uint32_t ad = smem_u32(&bB[(ks * 16 + lrow) * MP_LDB + wn + nt * 16 + lcof]);
                uint32_t r0, r1, r2, r3;
                asm volatile("ldmatrix.sync.aligned.m8n8.x4.trans.shared.b16 {%0,%1,%2,%3}, [%4];"
                             : "=r"(r0), "=r"(r1), "=r"(r2), "=r"(r3) : "r"(ad));
                fb[nt * 2][0] = r0; fb[nt * 2][1] = r1;
                fb[nt * 2 + 1][0] = r2; fb[nt * 2 + 1][1] = r3;
            }
#pragma unroll
            for (int t = 0; t < 2; t++)
#pragma unroll
                for (int j = 0; j < 8; j++)
                    asm volatile(
                        "mma.sync.aligned.m16n8k16.row.col.f32.f16.f16.f32 "
                        "{%0,%1,%2,%3}, {%4,%5,%6,%7}, {%8,%9}, {%0,%1,%2,%3};"
                        : "+f"(acc[t][j][0]), "+f"(acc[t][j][1]),
                          "+f"(acc[t][j][2]), "+f"(acc[t][j][3])
                        : "r"(fa[t][0]), "r"(fa[t][1]), "r"(fa[t][2]), "r"(fa[t][3]),
                          "r"(fb[j][0]), "r"(fb[j][1]));
        }
    }

    float rowdot[2][2] = {{0.f, 0.f}, {0.f, 0.f}};
#pragma unroll
    for (int t = 0; t < 2; t++) {
        const int mrow = e0 + wm + t * 16 + (lane >> 2);
#pragma unroll
        for (int j = 0; j < 8; j++) {
            const int nc = wn + j * 8 + (lane & 3) * 2;
            const float wx = __ldg(&wma[nc]);
            const float wy = __ldg(&wma[nc + 1]);
#pragma unroll
            for (int hf = 0; hf < 2; hf++) {
                const size_t m = (size_t)(mrow + hf * 8);
                float vx = acc[t][j][hf * 2 + 0];
                float vy = acc[t][j][hf * 2 + 1];
                const float2 d = __half22float2(*(const __half2*)&binput[m * 256 + nc]);
                vx = fmaxf(vx + d.x, 0.f);
                vy = fmaxf(vy + d.y, 0.f);
                *(__half2*)&msg_out[m * 256 + nc] = __floats2half2_rn(vx, vy);
                rowdot[t][hf] += vx * wx + vy * wy;
            }
        }
    }
    if (scores_out) {
#pragma unroll
        for (int t = 0; t < 2; t++)
#pragma unroll
            for (int hf = 0; hf < 2; hf++) {
                float v = rowdot[t][hf];
                v += __shfl_xor_sync(0xffffffffu, v, 1);
                v += __shfl_xor_sync(0xffffffffu, v, 2);
                if ((lane & 3) == 0)
                    atomicAdd(&sred[wm + t * 16 + hf * 8 + (lane >> 2)], v);
            }
        __syncthreads();
        if (tid < 64) scores_out[e0 + tid] = sred[tid];
    }
}

// ---------------------------------------------------------------------------
// atom_gather + fused fatoms conversion
// ---------------------------------------------------------------------------
__global__ void __launch_bounds__(256) atom_gather(
    const __half* __restrict__ msg, const int* __restrict__ agraph,
    const float* __restrict__ fa, __half* __restrict__ cat)
{
    const int ga   = (blockIdx.x * 256 + threadIdx.x) >> 5;
    const int lane = threadIdx.x & 31;
    if (ga >= N_ATOMS_) return;

    if (lane < 18) {
        const float* src = fa + (size_t)ga * AFD + lane * 8;
        __align__(16) __half hb[8];
#pragma unroll
        for (int k = 0; k < 8; k++) {
            const int c = lane * 8 + k;
            hb[k] = __float2half(c < AFD ? src[k] : 0.f);
        }
        *(uint4*)&cat[(size_t)ga * KCAT_P + lane * 8] = *(uint4*)hb;
    } else if (lane < 20) {
        uint4 z = make_uint4(0, 0, 0, 0);
        *(uint4*)&cat[(size_t)ga * KCAT_P + 400 + (lane - 18) * 8] = z;
    }

    float a[8] = {0, 0, 0, 0, 0, 0, 0, 0};
#pragma unroll
    for (int j = 0; j < 6; j++) {
        const int nb = agraph[ga * 6 + j];
        const uint4 rv = *(const uint4*)(msg + (size_t)nb * 256 + lane * 8);
        const float2 f0 = __half22float2(*(const __half2*)&rv.x);
        const float2 f1 = __half22float2(*(const __half2*)&rv.y);
        const float2 f2 = __half22float2(*(const __half2*)&rv.z);
        const float2 f3 = __half22float2(*(const __half2*)&rv.w);
        a[0] += f0.x; a[1] += f0.y; a[2] += f1.x; a[3] += f1.y;
        a[4] += f2.x; a[5] += f2.y; a[6] += f3.x; a[7] += f3.y;
    }
    uint4 ov;
    *(__half2*)&ov.x = __floats2half2_rn(a[0], a[1]);
    *(__half2*)&ov.y = __floats2half2_rn(a[2], a[3]);
    *(__half2*)&ov.z = __floats2half2_rn(a[4], a[5]);
    *(__half2*)&ov.w = __floats2half2_rn(a[6], a[7]);
    *(uint4*)(cat + (size_t)ga * KCAT_P + 144 + lane * 8) = ov;
}

// ---------------------------------------------------------------------------
// mol_attn v2: scores -> softmax -> relu(att@hB + b) rowsum + h rowsum -> out
// smem fp16 (55 KB -> 2 CTAs/SM). hWab[n][512] = [hW | hB].
// ---------------------------------------------------------------------------
#define MPAD 264
#define MOLATTN_SMEM ((3 * 32 * MPAD) * 2 + 32 * 32 * 4)

__global__ void __launch_bounds__(256, 2) mol_attn(
    const __half* __restrict__ atomh, const __half* __restrict__ hWab,
    const float* __restrict__ bias, float* __restrict__ out)
{
    extern __shared__ __align__(16) __half smx[];
    __half* sh = smx;                    // [32][MPAD] h
    __half* sw = smx + 32 * MPAD;        // [32][MPAD] hW
    __half* sb = smx + 2 * 32 * MPAD;    // [32][MPAD] hB
    float*  sa = (float*)(smx + 3 * 32 * MPAD);  // [32][32]

    const int b = blockIdx.x, tid = threadIdx.x;
    const __half* hb_ = atomh + (size_t)b * 32 * 256;
    const __half* wb_ = hWab  + (size_t)b * 32 * 512;

    // load h (32x256) and hWab (32x512) with 16B stores
#pragma unroll
    for (int it = 0; it < 4; it++) {
        const int id = tid + it * 256;          // 0..1023
        const int a = id >> 5, g = (id & 31) * 8;
        *(uint4*)&sh[a * MPAD + g] = *(const uint4*)&hb_[a * 256 + g];
    }
#pragma unroll
    for (int it = 0; it < 8; it++) {
        const int id = tid + it * 256;          // 0..2047
        const int a = id >> 6, g = (id & 63) * 8;
        const uint4 v = *(const uint4*)&wb_[a * 512 + g];
        if (g < 256) *(uint4*)&sw[a * MPAD + g] = v;
        else         *(uint4*)&sb[a * MPAD + (g - 256)] = v;
    }
    __syncthreads();

    // scores: 256 threads, 2x2 register tiles, fp16 loads
    {
        const int a0 = (tid >> 4) * 2;
        const int c0 = (tid & 15) * 2;
        float acc[2][2] = {{0.f, 0.f}, {0.f, 0.f}};
        for (int k = 0; k < 256; k += 4) {
            const uint2 aw0 = *(uint2*)&sw[a0 * MPAD + k];
            const uint2 aw1 = *(uint2*)&sw[(a0 + 1) * MPAD + k];
            const uint2 bh0 = *(uint2*)&sh[c0 * MPAD + k];
            const uint2 bh1 = *(uint2*)&sh[(c0 + 1) * MPAD + k];
            const float2 a00 = __half22float2(*(const __half2*)&aw0.x);
            const float2 a01 = __half22float2(*(const __half2*)&aw0.y);
            const float2 a10 = __half22float2(*(const __half2*)&aw1.x);
            const float2 a11 = __half22float2(*(const __half2*)&aw1.y);
            const float2 b00 = __half22float2(*(const __half2*)&bh0.x);
            const float2 b01 = __half22float2(*(const __half2*)&bh0.y);
            const float2 b10 = __half22float2(*(const __half2*)&bh1.x);
            const float2 b11 = __half22float2(*(const __half2*)&bh1.y);
            acc[0][0] += a00.x * b00.x + a00.y * b00.y + a01.x * b01.x + a01.y * b01.y;
            acc[0][1] += a00.x * b10.x + a00.y * b10.y + a01.x * b11.x + a01.y * b11.y;
            acc[1][0] += a10.x * b00.x + a10.y * b00.y + a11.x * b01.x + a11.y * b01.y;
            acc[1][1] += a10.x * b10.x + a10.y * b10.y + a11.x * b11.x + a11.y * b11.y;
        }
        sa[a0 * 32 + c0]           = acc[0][0];
        sa[a0 * 32 + c0 + 1]       = acc[0][1];
        sa[(a0 + 1) * 32 + c0]     = acc[1][0];
        sa[(a0 + 1) * 32 + c0 + 1] = acc[1][1];
    }
    __syncthreads();

    const int wid = tid >> 5, lane = tid & 31;
    for (int a = wid; a < 32; a += 8) {
        float v = sa[a * 32 + lane];
        float m = v;
#pragma unroll
        for (int o = 16; o > 0; o >>= 1) m = fmaxf(m, __shfl_xor_sync(0xffffffffu, m, o));
        float ev = expf(v - m);
        float sum = ev;
#pragma unroll
        for (int o = 16; o > 0; o >>= 1) sum += __shfl_xor_sync(0xffffffffu, sum, o);
        sa[a * 32 + lane] = ev / sum;
    }
    __syncthreads();

    // final: thread k computes relu(att@hB + b)[a][k] summed over a, + h sums
    const int k = tid;
    float acc[32];
#pragma unroll
    for (int a = 0; a < 32; a++) acc[a] = 0.f;
    for (int c = 0; c < 32; c++) {
        const float hv = __half2float(sb[c * MPAD + k]);
#pragma unroll
        for (int a = 0; a < 32; a++) acc[a] += sa[a * 32 + c] * hv;
    }
    const float bk = bias[k];
    float s = 0.f;
#pragma unroll
    for (int a = 0; a < 32; a++) {
        s += fmaxf(acc[a] + bk, 0.f);
        s += __half2float(sh[a * MPAD + k]);
    }
    out[(size_t)b * 256 + k] = s * (1.0f / 32.0f);
}

// ---------------------------------------------------------------------------
extern "C" void kernel_launch(void* const* d_in, const int* in_sizes, int n_in,
                              void* d_out, int out_size)
{
    const float* fatoms = (const float*)d_in[0];
    const float* fbonds = (const float*)d_in[1];
    const int*   agraph = (const int*)d_in[2];
    const int*   bgraph = (const int*)d_in[3];
    const float* W_i    = (const float*)d_in[5];
    const float* W_h    = (const float*)d_in[6];
    const float* W_o_w  = (const float*)d_in[7];
    const float* W_o_b  = (const float*)d_in[8];
    const float* W_a    = (const float*)d_in[9];
    const float* W_b_w  = (const float*)d_in[10];
    const float* W_b_b  = (const float*)d_in[11];
    const float* W_ma1  = (const float*)d_in[12];
    float* out = (float*)d_out;

    float* scratch = nullptr;
    cudaGetSymbolAddress((void**)&scratch, g_scratch);
    float* p = scratch;
    __half* binput_h = (__half*)p;            p += EH / 2;
    __half* msg0     = (__half*)p;            p += EH / 2;
    __half* msg1     = (__half*)p;            p += EH / 2;
    __half* fbonds_h = (__half*)p;            p += (size_t)E_BONDS * KIN_P / 2;
    __half* cat      = (__half*)p;            p += (size_t)N_ATOMS_ * KCAT_P / 2;
    __half* atomh_h  = (__half*)p;            p += NH / 2;
    __half* hWab     = (__half*)p;            p += NH;        // [N][512] fp16
    float*  scores0  = p;                     p += E_BONDS;
    float*  scores1  = p;                     p += E_BONDS;
    __half* Wall     = (__half*)p;
    __half* Wh_h = Wall;
    __half* Wi_p = Wh_h + HID * 256;
    __half* Wo_p = Wi_p + KIN_P * 256;
    __half* Wab  = Wo_p + KCAT_P * 256;       // [256][512]

    cudaFuncSetAttribute(mol_attn, cudaFuncAttributeMaxDynamicSharedMemorySize,
                         MOLATTN_SMEM);
    cudaFuncSetAttribute(mp_step<true>,  cudaFuncAttributeMaxDynamicSharedMemorySize, MP_SMEM);
    cudaFuncSetAttribute(mp_step<false>, cudaFuncAttributeMaxDynamicSharedMemorySize, MP_SMEM);
    cudaFuncSetAttribute(hgemm<false,true,false,true,true>,
                         cudaFuncAttributeMaxDynamicSharedMemorySize, HG_SMEM);
    cudaFuncSetAttribute(hgemm<true,true,true,false,false>,
                         cudaFuncAttributeMaxDynamicSharedMemorySize, HG_SMEM);
    cudaFuncSetAttribute(hgemm<false,false,true,false,false>,
                         cudaFuncAttributeMaxDynamicSharedMemorySize, HG_SMEM);

    const dim3 gE(E_BONDS / 128, 2);
    const dim3 gN(N_ATOMS_ / 128, 2);
    const dim3 gN4(N_ATOMS_ / 128, 4);

    fb_conv<<<(E_BONDS * 20 + 255) / 256, 256>>>(fbonds, fbonds_h);
    build_wi<<<(KIN_P * 256 + 255) / 256, 256>>>(W_i, Wi_p);
    w2h_all<<<(HID * 256 + 255) / 256, 256>>>(W_h, Wh_h, scores0, E_BONDS);

    // G1: binput_h(raw only) = fbonds_h @ Wi_p, fused scores0 (post-relu)
    hgemm<false, true, false, true, true><<<gE, 256, HG_SMEM>>>(
        E_BONDS, KIN_P, fbonds_h, KIN_P, Wi_p, 256, nullptr,
        nullptr, 256, binput_h, W_ma1, scores0);

    build_wo<<<(KCAT_P * 256 + 255) / 256, 256>>>(W_o_w, Wo_p);
    build_wab<<<(HID * 512 + 255) / 256, 256>>>(W_a, W_b_w, Wab);

    // 3 fused message-passing steps; step 1 gathers relu(binput)
    mp_step<true><<<E_BONDS / 64, 256, MP_SMEM>>>(binput_h, bgraph, scores0, Wh_h,
                                                  binput_h, msg1, W_ma1, scores1);
    mp_step<false><<<E_BONDS / 64, 256, MP_SMEM>>>(msg1, bgraph, scores1, Wh_h,
                                                   binput_h, msg0, W_ma1, scores0);
    mp_step<false><<<E_BONDS / 64, 256, MP_SMEM>>>(msg0, bgraph, scores0, Wh_h,
                                                   binput_h, msg1, W_ma1, nullptr);

    // atom readout
    atom_gather<<<N_ATOMS_ / 8, 256>>>(msg1, agraph, fatoms, cat);
    hgemm<true, true, true, false, false><<<gN, 256, HG_SMEM>>>(
        N_ATOMS_, KCAT_P, cat, KCAT_P, Wo_p, 256, W_o_b,
        atomh_h, 256, nullptr, nullptr, nullptr);

    // fused [hW | hB] GEMM (N=512)
    hgemm<false, false, true, false, false><<<gN4, 256, HG_SMEM>>>(
        N_ATOMS_, HID, atomh_h, HID, Wab, 512, nullptr,
        hWab, 512, nullptr, nullptr, nullptr);

    // molecule attention -> final output directly
    mol_attn<<<BMOL, 256, MOLATTN_SMEM>>>(atomh_h, hWab, W_b_b, out);
}